// round 4
// baseline (speedup 1.0000x reference)
#include <cuda_runtime.h>
#include <math.h>

// Fixed problem: B=128, T=514, D=8, H=64, L=2, IN=17, W=512, N=65536
// out layout: [0,524288) residuals (B,W,D) | [524288,524416) logdet (B,)
//             [524416,8913024) hist_jac (D,N,16)
#define SLOPE 0.2f
#define S 68              // smem row stride (floats)
#define SMEM_FLOATS 23700
#define SMEM_BYTES  (SMEM_FLOATS * 4)

// smem float offsets (all multiples of 4 -> 16B aligned)
#define OFF_X   0          // [17][S]  layer-0 inputs (k-major)
#define OFF_B0  1156       // [64][S]  act0
#define OFF_B1  5508       // [64][S]  act1
#define OFF_B2  9860       // [64][S]  g / g1
#define OFF_B3  14212      // [64][S]  g2
#define OFF_W   18564      // [64][S]  current weight tile (contraction-major)
#define OFF_OUT 22916      // [8][64]  per-ty partial head sums
#define OFF_J   23428      // [16]     per-tx logdet partials
#define OFF_SB0 23444
#define OFF_SB1 23508
#define OFF_SB2 23572
#define OFF_SWO 23636

__device__ float g_partials[8192];   // [d][tile] (8 x 1024)

// acc[i] (i=0..7): output (ty*8+i), 4 samples (tx*4..+3).
// A, Wc are contraction-major [K][S].
__device__ __forceinline__ void gemm_acc(const float* __restrict__ A,
                                         const float* __restrict__ Wc,
                                         int K, int tx, int ty, float4* acc) {
    const float* ap = A + tx * 4;
    const float* wp = Wc + ty * 8;
#pragma unroll 4
    for (int k = 0; k < K; ++k) {
        float4 a  = *(const float4*)(ap + k * S);
        float4 w0 = *(const float4*)(wp + k * S);
        float4 w1 = *(const float4*)(wp + k * S + 4);
#define FMA4(I, WS)                                  \
        acc[I].x = fmaf(WS, a.x, acc[I].x);          \
        acc[I].y = fmaf(WS, a.y, acc[I].y);          \
        acc[I].z = fmaf(WS, a.z, acc[I].z);          \
        acc[I].w = fmaf(WS, a.w, acc[I].w)
        FMA4(0, w0.x); FMA4(1, w0.y); FMA4(2, w0.z); FMA4(3, w0.w);
        FMA4(4, w1.x); FMA4(5, w1.y); FMA4(6, w1.z); FMA4(7, w1.w);
#undef FMA4
    }
}

#define GETC(v, j) ((j) == 0 ? (v).x : (j) == 1 ? (v).y : (j) == 2 ? (v).z : (v).w)

__global__ void __launch_bounds__(128)
mlp_tile_kernel(const float* __restrict__ x,
                const float* __restrict__ W0, const float* __restrict__ b0,
                const float* __restrict__ W1, const float* __restrict__ b1,
                const float* __restrict__ W2, const float* __restrict__ b2,
                const float* __restrict__ Wo, const float* __restrict__ bo,
                float* __restrict__ out)
{
    extern __shared__ float sm[];
    const int tid  = threadIdx.x;
    const int tx   = tid & 15;      // sample group (4 samples)
    const int ty   = tid >> 4;      // output group (8 outputs)
    const int tile = blockIdx.x;    // 0..1023  (64 samples each)
    const int d    = blockIdx.y;    // 0..7

    // ---------------- phase 1: inputs, W0^T, biases ----------------
    {   // 64 samples x 16 contiguous floats; sample s, half = tid>>6
        const int s = tid & 63, half = tid >> 6;
        const int n = tile * 64 + s;
        const float* xb = x + (size_t)((n >> 9) * 514 + (n & 511)) * 8;
        float4 v0 = *(const float4*)(xb + half * 8);
        float4 v1 = *(const float4*)(xb + half * 8 + 4);
        float* dst = sm + OFF_X + s;
        dst[(half * 8 + 0) * S] = v0.x;  dst[(half * 8 + 1) * S] = v0.y;
        dst[(half * 8 + 2) * S] = v0.z;  dst[(half * 8 + 3) * S] = v0.w;
        dst[(half * 8 + 4) * S] = v1.x;  dst[(half * 8 + 5) * S] = v1.y;
        dst[(half * 8 + 6) * S] = v1.z;  dst[(half * 8 + 7) * S] = v1.w;
        if (half == 0) dst[16 * S] = xb[16 + d];
    }
    for (int i = tid; i < 64 * 17; i += 128) {         // W0^T: [k][h]
        int h = i / 17, k = i - 17 * h;
        sm[OFF_W + k * S + h] = W0[d * 1088 + i];
    }
    if (tid < 64) {
        sm[OFF_SB0 + tid] = b0[d * 64 + tid];
        sm[OFF_SB1 + tid] = b1[d * 64 + tid];
        sm[OFF_SB2 + tid] = b2[d * 64 + tid];
        sm[OFF_SWO + tid] = Wo[d * 64 + tid];
    }
    __syncthreads();

    float4 acc[8];

    // ---------------- layer 0: K=17 -> act0 ----------------
#pragma unroll
    for (int i = 0; i < 8; ++i) {
        float bi = sm[OFF_SB0 + ty * 8 + i];
        acc[i] = make_float4(bi, bi, bi, bi);
    }
    gemm_acc(sm + OFF_X, sm + OFF_W, 17, tx, ty, acc);
#pragma unroll
    for (int i = 0; i < 8; ++i) {
        float4 v = acc[i];
        v.x = v.x > 0.f ? v.x : v.x * SLOPE;
        v.y = v.y > 0.f ? v.y : v.y * SLOPE;
        v.z = v.z > 0.f ? v.z : v.z * SLOPE;
        v.w = v.w > 0.f ? v.w : v.w * SLOPE;
        *(float4*)(sm + OFF_B0 + (ty * 8 + i) * S + tx * 4) = v;
    }
    __syncthreads();

    // ---------------- layer 1 ----------------
    for (int i = tid; i < 4096; i += 128) {            // W1^T
        int h = i >> 6, k = i & 63;
        sm[OFF_W + k * S + h] = W1[d * 4096 + i];
    }
    __syncthreads();
#pragma unroll
    for (int i = 0; i < 8; ++i) {
        float bi = sm[OFF_SB1 + ty * 8 + i];
        acc[i] = make_float4(bi, bi, bi, bi);
    }
    gemm_acc(sm + OFF_B0, sm + OFF_W, 64, tx, ty, acc);
#pragma unroll
    for (int i = 0; i < 8; ++i) {
        float4 v = acc[i];
        v.x = v.x > 0.f ? v.x : v.x * SLOPE;
        v.y = v.y > 0.f ? v.y : v.y * SLOPE;
        v.z = v.z > 0.f ? v.z : v.z * SLOPE;
        v.w = v.w > 0.f ? v.w : v.w * SLOPE;
        *(float4*)(sm + OFF_B1 + (ty * 8 + i) * S + tx * 4) = v;
    }
    __syncthreads();

    // ---------------- layer 2 + head: g = Wo*m2, partial out ----------------
    for (int i = tid; i < 4096; i += 128) {            // W2^T
        int h = i >> 6, k = i & 63;
        sm[OFF_W + k * S + h] = W2[d * 4096 + i];
    }
    __syncthreads();
#pragma unroll
    for (int i = 0; i < 8; ++i) {
        float bi = sm[OFF_SB2 + ty * 8 + i];
        acc[i] = make_float4(bi, bi, bi, bi);
    }
    gemm_acc(sm + OFF_B1, sm + OFF_W, 64, tx, ty, acc);
    {
        float4 osum = make_float4(0.f, 0.f, 0.f, 0.f);
#pragma unroll
        for (int i = 0; i < 8; ++i) {
            float wo = sm[OFF_SWO + ty * 8 + i];
            float4 h2 = acc[i];
            float4 g;
            g.x = wo * (h2.x > 0.f ? 1.f : SLOPE);
            g.y = wo * (h2.y > 0.f ? 1.f : SLOPE);
            g.z = wo * (h2.z > 0.f ? 1.f : SLOPE);
            g.w = wo * (h2.w > 0.f ? 1.f : SLOPE);
            osum.x = fmaf(g.x, h2.x, osum.x);
            osum.y = fmaf(g.y, h2.y, osum.y);
            osum.z = fmaf(g.z, h2.z, osum.z);
            osum.w = fmaf(g.w, h2.w, osum.w);
            *(float4*)(sm + OFF_B2 + (ty * 8 + i) * S + tx * 4) = g;
        }
        *(float4*)(sm + OFF_OUT + ty * 64 + tx * 4) = osum;
    }
    __syncthreads();

    // residual store + W2 (row-major) load
    for (int i = tid; i < 4096; i += 128)
        sm[OFF_W + (i >> 6) * S + (i & 63)] = W2[d * 4096 + i];
    if (tid < 64) {
        float r = bo[d];
#pragma unroll
        for (int q = 0; q < 8; ++q) r += sm[OFF_OUT + q * 64 + tid];
        out[(size_t)(tile * 64 + tid) * 8 + d] = r;
    }
    __syncthreads();

    // ---------------- backward: g2 = (g @ W2) * m1 ----------------
#pragma unroll
    for (int i = 0; i < 8; ++i) acc[i] = make_float4(0.f, 0.f, 0.f, 0.f);
    gemm_acc(sm + OFF_B2, sm + OFF_W, 64, tx, ty, acc);
#pragma unroll
    for (int i = 0; i < 8; ++i) {
        float4 a1 = *(const float4*)(sm + OFF_B1 + (ty * 8 + i) * S + tx * 4);
        float4 v = acc[i];
        v.x *= (a1.x > 0.f ? 1.f : SLOPE);
        v.y *= (a1.y > 0.f ? 1.f : SLOPE);
        v.z *= (a1.z > 0.f ? 1.f : SLOPE);
        v.w *= (a1.w > 0.f ? 1.f : SLOPE);
        *(float4*)(sm + OFF_B3 + (ty * 8 + i) * S + tx * 4) = v;
    }
    __syncthreads();

    // ---------------- backward: g1 = (g2 @ W1) * m0 ----------------
    for (int i = tid; i < 4096; i += 128)
        sm[OFF_W + (i >> 6) * S + (i & 63)] = W1[d * 4096 + i];
    __syncthreads();
#pragma unroll
    for (int i = 0; i < 8; ++i) acc[i] = make_float4(0.f, 0.f, 0.f, 0.f);
    gemm_acc(sm + OFF_B3, sm + OFF_W, 64, tx, ty, acc);
#pragma unroll
    for (int i = 0; i < 8; ++i) {
        float4 a0 = *(const float4*)(sm + OFF_B0 + (ty * 8 + i) * S + tx * 4);
        float4 v = acc[i];
        v.x *= (a0.x > 0.f ? 1.f : SLOPE);
        v.y *= (a0.y > 0.f ? 1.f : SLOPE);
        v.z *= (a0.z > 0.f ? 1.f : SLOPE);
        v.w *= (a0.w > 0.f ? 1.f : SLOPE);
        *(float4*)(sm + OFF_B2 + (ty * 8 + i) * S + tx * 4) = v;
    }
    __syncthreads();

    // ---------------- jac = g1 @ W0 (17 outputs, pad to 24 with zeros) ----------------
    for (int i = tid; i < 64 * 24; i += 128) {          // W0 row-major, zero pad
        int h = i / 24, k = i - 24 * h;
        sm[OFF_W + h * S + k] = (k < 17) ? W0[d * 1088 + h * 17 + k] : 0.f;
    }
    __syncthreads();
    if (ty < 3) {
#pragma unroll
        for (int i = 0; i < 8; ++i) acc[i] = make_float4(0.f, 0.f, 0.f, 0.f);
        gemm_acc(sm + OFF_B2, sm + OFF_W, 64, tx, ty, acc);
        if (ty < 2) {
            // hist_jac: k = ty*8 .. ty*8+7 for 4 samples
#pragma unroll
            for (int j = 0; j < 4; ++j) {
                int n = tile * 64 + tx * 4 + j;
                float* p = out + 524416 + ((size_t)d * 65536 + n) * 16 + ty * 8;
                *(float4*)p = make_float4(GETC(acc[0], j), GETC(acc[1], j),
                                          GETC(acc[2], j), GETC(acc[3], j));
                *(float4*)(p + 4) = make_float4(GETC(acc[4], j), GETC(acc[5], j),
                                                GETC(acc[6], j), GETC(acc[7], j));
            }
        } else {
            // k=16 column -> logdet contribution for 4 samples (fixed order)
            float4 j16 = acc[0];
            float sj = logf(fabsf(j16.x)) + logf(fabsf(j16.y)) +
                       logf(fabsf(j16.z)) + logf(fabsf(j16.w));
            sm[OFF_J + tx] = sj;
        }
    }
    __syncthreads();
    if (tid == 0) {
        float sj = 0.f;
#pragma unroll
        for (int q = 0; q < 16; ++q) sj += sm[OFF_J + q];
        g_partials[d * 1024 + tile] = sj;
    }
}

// logdet[b] = fixed-order sum over d(8) x 8 tiles of batch b
__global__ void logdet_reduce_kernel(float* __restrict__ out) {
    const int b = threadIdx.x;    // 128 threads
    float s = 0.f;
#pragma unroll
    for (int d = 0; d < 8; ++d)
#pragma unroll
        for (int q = 0; q < 8; ++q)
            s += g_partials[d * 1024 + b * 8 + q];
    out[524288 + b] = s;
}

extern "C" void kernel_launch(void* const* d_in, const int* in_sizes, int n_in,
                              void* d_out, int out_size) {
    const float* x  = (const float*)d_in[0];
    const float* W0 = (const float*)d_in[1];
    const float* b0 = (const float*)d_in[2];
    const float* W1 = (const float*)d_in[3];
    const float* b1 = (const float*)d_in[4];
    const float* W2 = (const float*)d_in[5];
    const float* b2 = (const float*)d_in[6];
    const float* Wo = (const float*)d_in[7];
    const float* bo = (const float*)d_in[8];
    float* out = (float*)d_out;

    cudaFuncSetAttribute(mlp_tile_kernel,
                         cudaFuncAttributeMaxDynamicSharedMemorySize, SMEM_BYTES);
    dim3 grid(1024, 8);
    mlp_tile_kernel<<<grid, 128, SMEM_BYTES>>>(x, W0, b0, W1, b1, W2, b2, Wo, bo, out);
    logdet_reduce_kernel<<<1, 128>>>(out);
}

// round 5
// speedup vs baseline: 1.3121x; 1.3121x over previous
#include <cuda_runtime.h>
#include <math.h>

// Fixed problem: B=128, T=514, D=8, H=64, L=2, IN=17, W=512, N=65536
// out layout: [0,524288) residuals (B,W,D) | [524288,524416) logdet (B,)
//             [524416,8913024) hist_jac (D,N,16)
#define SLOPE 0.2f
#define S 68              // smem row stride (floats); k*S stays 16B-aligned
#define SMEM_FLOATS 23716
#define SMEM_BYTES  (SMEM_FLOATS * 4)

#define OFF_X   0          // [17][S]  layer-0 inputs (k-major)
#define OFF_B0  1156       // [64][S]  act0
#define OFF_B1  5508       // [64][S]  act1
#define OFF_B2  9860       // [64][S]  g / g1
#define OFF_B3  14212      // [64][S]  g2
#define OFF_W   18564      // [64][S]  current weight tile (contraction-major)
#define OFF_OUT 22916      // [8][64]  per-ty partial head sums
#define OFF_J   23428      // [32]     per-txj logdet partials
#define OFF_SB0 23460
#define OFF_SB1 23524
#define OFF_SB2 23588
#define OFF_SWO 23652

typedef unsigned long long u64;

__device__ float g_partials[8192];   // [d][tile] (8 x 1024)

// ---- packed f32x2 primitives ----
__device__ __forceinline__ u64 ffma2(u64 a, u64 b, u64 c) {
    u64 d; asm("fma.rn.f32x2 %0, %1, %2, %3;" : "=l"(d) : "l"(a), "l"(b), "l"(c)); return d;
}
__device__ __forceinline__ u64 pack2(float x, float y) {
    u64 r; asm("mov.b64 %0, {%1, %2};" : "=l"(r) : "f"(x), "f"(y)); return r;
}
__device__ __forceinline__ float2 unpk(u64 v) {
    float2 r; asm("mov.b64 {%0, %1}, %2;" : "=f"(r.x), "=f"(r.y) : "l"(v)); return r;
}
__device__ __forceinline__ float lk(float v) { return v > 0.f ? v : v * SLOPE; }
__device__ __forceinline__ float mk(float a) { return a > 0.f ? 1.f : SLOPE; }

// Packed GEMM: 8 outputs (4 packed pairs) x 4 samples per thread.
// acc[p*4+j]: lo = output base+2p, hi = base+2p+1, sample tx*4+j.
// A, W contraction-major [K][S]; W pairs load directly as u64.
__device__ __forceinline__ void gemm16(const float* __restrict__ A,
                                       const float* __restrict__ Wc,
                                       int K, int tx, int ty, u64* acc) {
    const float* ap = A + tx * 4;
    const float* wp = Wc + ty * 8;
#pragma unroll 4
    for (int k = 0; k < K; ++k) {
        float4 a = *(const float4*)(ap + k * S);
        ulonglong2 wA = *(const ulonglong2*)(wp + k * S);
        ulonglong2 wB = *(const ulonglong2*)(wp + k * S + 4);
        u64 a0 = pack2(a.x, a.x), a1 = pack2(a.y, a.y);
        u64 a2 = pack2(a.z, a.z), a3 = pack2(a.w, a.w);
        acc[0]  = ffma2(wA.x, a0, acc[0]);   acc[1]  = ffma2(wA.x, a1, acc[1]);
        acc[2]  = ffma2(wA.x, a2, acc[2]);   acc[3]  = ffma2(wA.x, a3, acc[3]);
        acc[4]  = ffma2(wA.y, a0, acc[4]);   acc[5]  = ffma2(wA.y, a1, acc[5]);
        acc[6]  = ffma2(wA.y, a2, acc[6]);   acc[7]  = ffma2(wA.y, a3, acc[7]);
        acc[8]  = ffma2(wB.x, a0, acc[8]);   acc[9]  = ffma2(wB.x, a1, acc[9]);
        acc[10] = ffma2(wB.x, a2, acc[10]);  acc[11] = ffma2(wB.x, a3, acc[11]);
        acc[12] = ffma2(wB.y, a0, acc[12]);  acc[13] = ffma2(wB.y, a1, acc[13]);
        acc[14] = ffma2(wB.y, a2, acc[14]);  acc[15] = ffma2(wB.y, a3, acc[15]);
    }
}

__global__ void __launch_bounds__(128)
mlp_tile_kernel(const float* __restrict__ x,
                const float* __restrict__ W0, const float* __restrict__ b0,
                const float* __restrict__ W1, const float* __restrict__ b1,
                const float* __restrict__ W2, const float* __restrict__ b2,
                const float* __restrict__ Wo, const float* __restrict__ bo,
                float* __restrict__ out)
{
    extern __shared__ float sm[];
    const int tid  = threadIdx.x;
    const int tx   = tid & 15;
    const int ty   = tid >> 4;
    const int tile = blockIdx.x;
    const int d    = blockIdx.y;

    // ---------------- phase 1: inputs, W0^T, biases ----------------
    {
        const int s = tid & 63, half = tid >> 6;
        const int n = tile * 64 + s;
        const float* xb = x + (size_t)((n >> 9) * 514 + (n & 511)) * 8;
        float4 v0 = *(const float4*)(xb + half * 8);
        float4 v1 = *(const float4*)(xb + half * 8 + 4);
        float* dst = sm + OFF_X + s;
        dst[(half * 8 + 0) * S] = v0.x;  dst[(half * 8 + 1) * S] = v0.y;
        dst[(half * 8 + 2) * S] = v0.z;  dst[(half * 8 + 3) * S] = v0.w;
        dst[(half * 8 + 4) * S] = v1.x;  dst[(half * 8 + 5) * S] = v1.y;
        dst[(half * 8 + 6) * S] = v1.z;  dst[(half * 8 + 7) * S] = v1.w;
        if (half == 0) dst[16 * S] = xb[16 + d];
    }
    for (int i = tid; i < 64 * 17; i += 128) {          // W0^T: [k][h]
        int h = i / 17, k = i - 17 * h;
        sm[OFF_W + k * S + h] = W0[d * 1088 + i];
    }
    if (tid < 64) {
        sm[OFF_SB0 + tid] = b0[d * 64 + tid];
        sm[OFF_SB1 + tid] = b1[d * 64 + tid];
        sm[OFF_SB2 + tid] = b2[d * 64 + tid];
        sm[OFF_SWO + tid] = Wo[d * 64 + tid];
    }
    __syncthreads();

    u64 acc[16];

    // ---------------- layer 0: K=17 -> act0 ----------------
#pragma unroll
    for (int p = 0; p < 4; ++p) {
        u64 bp = *(const u64*)(sm + OFF_SB0 + ty * 8 + 2 * p);
        acc[p * 4 + 0] = bp; acc[p * 4 + 1] = bp; acc[p * 4 + 2] = bp; acc[p * 4 + 3] = bp;
    }
    gemm16(sm + OFF_X, sm + OFF_W, 17, tx, ty, acc);
#pragma unroll
    for (int p = 0; p < 4; ++p) {
        float2 v0 = unpk(acc[p * 4 + 0]), v1 = unpk(acc[p * 4 + 1]);
        float2 v2 = unpk(acc[p * 4 + 2]), v3 = unpk(acc[p * 4 + 3]);
        *(float4*)(sm + OFF_B0 + (ty * 8 + 2 * p) * S + tx * 4) =
            make_float4(lk(v0.x), lk(v1.x), lk(v2.x), lk(v3.x));
        *(float4*)(sm + OFF_B0 + (ty * 8 + 2 * p + 1) * S + tx * 4) =
            make_float4(lk(v0.y), lk(v1.y), lk(v2.y), lk(v3.y));
    }
    __syncthreads();

    // ---------------- layer 1 ----------------
    for (int i = tid; i < 4096; i += 128)               // W1^T
        sm[OFF_W + (i & 63) * S + (i >> 6)] = W1[d * 4096 + i];
    __syncthreads();
#pragma unroll
    for (int p = 0; p < 4; ++p) {
        u64 bp = *(const u64*)(sm + OFF_SB1 + ty * 8 + 2 * p);
        acc[p * 4 + 0] = bp; acc[p * 4 + 1] = bp; acc[p * 4 + 2] = bp; acc[p * 4 + 3] = bp;
    }
    gemm16(sm + OFF_B0, sm + OFF_W, 64, tx, ty, acc);
#pragma unroll
    for (int p = 0; p < 4; ++p) {
        float2 v0 = unpk(acc[p * 4 + 0]), v1 = unpk(acc[p * 4 + 1]);
        float2 v2 = unpk(acc[p * 4 + 2]), v3 = unpk(acc[p * 4 + 3]);
        *(float4*)(sm + OFF_B1 + (ty * 8 + 2 * p) * S + tx * 4) =
            make_float4(lk(v0.x), lk(v1.x), lk(v2.x), lk(v3.x));
        *(float4*)(sm + OFF_B1 + (ty * 8 + 2 * p + 1) * S + tx * 4) =
            make_float4(lk(v0.y), lk(v1.y), lk(v2.y), lk(v3.y));
    }
    __syncthreads();

    // ---------------- layer 2 + head: g = Wo*m2, partial out ----------------
    for (int i = tid; i < 4096; i += 128)               // W2^T
        sm[OFF_W + (i & 63) * S + (i >> 6)] = W2[d * 4096 + i];
    __syncthreads();
#pragma unroll
    for (int p = 0; p < 4; ++p) {
        u64 bp = *(const u64*)(sm + OFF_SB2 + ty * 8 + 2 * p);
        acc[p * 4 + 0] = bp; acc[p * 4 + 1] = bp; acc[p * 4 + 2] = bp; acc[p * 4 + 3] = bp;
    }
    gemm16(sm + OFF_B1, sm + OFF_W, 64, tx, ty, acc);
    {
        float4 osum = make_float4(0.f, 0.f, 0.f, 0.f);
#pragma unroll
        for (int p = 0; p < 4; ++p) {
            float wl = sm[OFF_SWO + ty * 8 + 2 * p];
            float wh = sm[OFF_SWO + ty * 8 + 2 * p + 1];
            float2 v0 = unpk(acc[p * 4 + 0]), v1 = unpk(acc[p * 4 + 1]);
            float2 v2 = unpk(acc[p * 4 + 2]), v3 = unpk(acc[p * 4 + 3]);
            float gl0 = wl * mk(v0.x), gl1 = wl * mk(v1.x), gl2 = wl * mk(v2.x), gl3 = wl * mk(v3.x);
            float gh0 = wh * mk(v0.y), gh1 = wh * mk(v1.y), gh2 = wh * mk(v2.y), gh3 = wh * mk(v3.y);
            osum.x = fmaf(gl0, v0.x, fmaf(gh0, v0.y, osum.x));
            osum.y = fmaf(gl1, v1.x, fmaf(gh1, v1.y, osum.y));
            osum.z = fmaf(gl2, v2.x, fmaf(gh2, v2.y, osum.z));
            osum.w = fmaf(gl3, v3.x, fmaf(gh3, v3.y, osum.w));
            *(float4*)(sm + OFF_B2 + (ty * 8 + 2 * p) * S + tx * 4) =
                make_float4(gl0, gl1, gl2, gl3);
            *(float4*)(sm + OFF_B2 + (ty * 8 + 2 * p + 1) * S + tx * 4) =
                make_float4(gh0, gh1, gh2, gh3);
        }
        *(float4*)(sm + OFF_OUT + ty * 64 + tx * 4) = osum;
    }
    __syncthreads();

    // residual store + W2 (row-major, vectorized) stage
    {
        const float4* src = (const float4*)(W2 + d * 4096);
#pragma unroll
        for (int q = 0; q < 8; ++q) {
            int i4 = q * 128 + tid;
            float4 v = src[i4];
            *(float4*)(sm + OFF_W + (i4 >> 4) * S + (i4 & 15) * 4) = v;
        }
    }
    if (tid < 64) {
        float r = bo[d];
#pragma unroll
        for (int q = 0; q < 8; ++q) r += sm[OFF_OUT + q * 64 + tid];
        out[(size_t)(tile * 64 + tid) * 8 + d] = r;
    }
    __syncthreads();

    // ---------------- backward: g2 = (g @ W2) * m1 ----------------
#pragma unroll
    for (int i = 0; i < 16; ++i) acc[i] = 0ull;
    gemm16(sm + OFF_B2, sm + OFF_W, 64, tx, ty, acc);
#pragma unroll
    for (int p = 0; p < 4; ++p) {
        float4 al = *(const float4*)(sm + OFF_B1 + (ty * 8 + 2 * p) * S + tx * 4);
        float4 ah = *(const float4*)(sm + OFF_B1 + (ty * 8 + 2 * p + 1) * S + tx * 4);
        float2 v0 = unpk(acc[p * 4 + 0]), v1 = unpk(acc[p * 4 + 1]);
        float2 v2 = unpk(acc[p * 4 + 2]), v3 = unpk(acc[p * 4 + 3]);
        *(float4*)(sm + OFF_B3 + (ty * 8 + 2 * p) * S + tx * 4) =
            make_float4(v0.x * mk(al.x), v1.x * mk(al.y), v2.x * mk(al.z), v3.x * mk(al.w));
        *(float4*)(sm + OFF_B3 + (ty * 8 + 2 * p + 1) * S + tx * 4) =
            make_float4(v0.y * mk(ah.x), v1.y * mk(ah.y), v2.y * mk(ah.z), v3.y * mk(ah.w));
    }
    __syncthreads();

    // ---------------- backward: g1 = (g2 @ W1) * m0 ----------------
    {
        const float4* src = (const float4*)(W1 + d * 4096);
#pragma unroll
        for (int q = 0; q < 8; ++q) {
            int i4 = q * 128 + tid;
            float4 v = src[i4];
            *(float4*)(sm + OFF_W + (i4 >> 4) * S + (i4 & 15) * 4) = v;
        }
    }
    __syncthreads();
#pragma unroll
    for (int i = 0; i < 16; ++i) acc[i] = 0ull;
    gemm16(sm + OFF_B3, sm + OFF_W, 64, tx, ty, acc);
#pragma unroll
    for (int p = 0; p < 4; ++p) {
        float4 al = *(const float4*)(sm + OFF_B0 + (ty * 8 + 2 * p) * S + tx * 4);
        float4 ah = *(const float4*)(sm + OFF_B0 + (ty * 8 + 2 * p + 1) * S + tx * 4);
        float2 v0 = unpk(acc[p * 4 + 0]), v1 = unpk(acc[p * 4 + 1]);
        float2 v2 = unpk(acc[p * 4 + 2]), v3 = unpk(acc[p * 4 + 3]);
        *(float4*)(sm + OFF_B2 + (ty * 8 + 2 * p) * S + tx * 4) =
            make_float4(v0.x * mk(al.x), v1.x * mk(al.y), v2.x * mk(al.z), v3.x * mk(al.w));
        *(float4*)(sm + OFF_B2 + (ty * 8 + 2 * p + 1) * S + tx * 4) =
            make_float4(v0.y * mk(ah.x), v1.y * mk(ah.y), v2.y * mk(ah.z), v3.y * mk(ah.w));
    }
    __syncthreads();

    // ---------------- jac = g1 @ W0 (24 padded outputs, 96 threads) ----------------
    for (int i = tid; i < 64 * 24; i += 128) {          // W0 row-major (contraction-major here)
        int h = i / 24, c = i - 24 * h;
        sm[OFF_W + h * S + c] = (c < 17) ? W0[d * 1088 + h * 17 + c] : 0.f;
    }
    __syncthreads();
    {
        const int tyj = tid >> 5;        // 0..3 (3 used)
        const int txj = tid & 31;        // 2 samples each
        if (tyj < 3) {
            u64 acc2[8];                 // [pair p][sample j]
#pragma unroll
            for (int i = 0; i < 8; ++i) acc2[i] = 0ull;
            const float* ap = sm + OFF_B2 + txj * 2;
            const float* wp = sm + OFF_W + tyj * 8;
#pragma unroll 4
            for (int k = 0; k < 64; ++k) {
                float2 a = *(const float2*)(ap + k * S);
                ulonglong2 wA = *(const ulonglong2*)(wp + k * S);
                ulonglong2 wB = *(const ulonglong2*)(wp + k * S + 4);
                u64 a0 = pack2(a.x, a.x), a1 = pack2(a.y, a.y);
                acc2[0] = ffma2(wA.x, a0, acc2[0]);  acc2[1] = ffma2(wA.x, a1, acc2[1]);
                acc2[2] = ffma2(wA.y, a0, acc2[2]);  acc2[3] = ffma2(wA.y, a1, acc2[3]);
                acc2[4] = ffma2(wB.x, a0, acc2[4]);  acc2[5] = ffma2(wB.x, a1, acc2[5]);
                acc2[6] = ffma2(wB.y, a0, acc2[6]);  acc2[7] = ffma2(wB.y, a1, acc2[7]);
            }
            if (tyj < 2) {
#pragma unroll
                for (int j = 0; j < 2; ++j) {
                    int n = tile * 64 + txj * 2 + j;
                    float2 p0 = unpk(acc2[0 + j]), p1 = unpk(acc2[2 + j]);
                    float2 p2 = unpk(acc2[4 + j]), p3 = unpk(acc2[6 + j]);
                    float* dst = out + 524416 + ((size_t)d * 65536 + n) * 16 + tyj * 8;
                    *(float4*)dst       = make_float4(p0.x, p0.y, p1.x, p1.y);
                    *(float4*)(dst + 4) = make_float4(p2.x, p2.y, p3.x, p3.y);
                }
            } else {
                float2 j0 = unpk(acc2[0]);   // output 16 is lo of pair 0
                float2 j1 = unpk(acc2[1]);
                sm[OFF_J + txj] = logf(fabsf(j0.x)) + logf(fabsf(j1.x));
            }
        }
    }
    __syncthreads();
    if (tid == 0) {
        float sj = 0.f;
#pragma unroll
        for (int q = 0; q < 32; ++q) sj += sm[OFF_J + q];
        g_partials[d * 1024 + tile] = sj;
    }
}

// logdet[b] = fixed-order sum over d(8) x 8 tiles of batch b
__global__ void logdet_reduce_kernel(float* __restrict__ out) {
    const int b = threadIdx.x;    // 128 threads
    float s = 0.f;
#pragma unroll
    for (int d = 0; d < 8; ++d)
#pragma unroll
        for (int q = 0; q < 8; ++q)
            s += g_partials[d * 1024 + b * 8 + q];
    out[524288 + b] = s;
}

extern "C" void kernel_launch(void* const* d_in, const int* in_sizes, int n_in,
                              void* d_out, int out_size) {
    const float* x  = (const float*)d_in[0];
    const float* W0 = (const float*)d_in[1];
    const float* b0 = (const float*)d_in[2];
    const float* W1 = (const float*)d_in[3];
    const float* b1 = (const float*)d_in[4];
    const float* W2 = (const float*)d_in[5];
    const float* b2 = (const float*)d_in[6];
    const float* Wo = (const float*)d_in[7];
    const float* bo = (const float*)d_in[8];
    float* out = (float*)d_out;

    cudaFuncSetAttribute(mlp_tile_kernel,
                         cudaFuncAttributeMaxDynamicSharedMemorySize, SMEM_BYTES);
    dim3 grid(1024, 8);
    mlp_tile_kernel<<<grid, 128, SMEM_BYTES>>>(x, W0, b0, W1, b1, W2, b2, Wo, bo, out);
    logdet_reduce_kernel<<<1, 128>>>(out);
}

// round 6
// speedup vs baseline: 1.5089x; 1.1500x over previous
#include <cuda_runtime.h>
#include <math.h>

// Fixed problem: B=128, T=514, D=8, H=64, L=2, IN=17, W=512, N=65536
// out layout: [0,524288) residuals (B,W,D) | [524288,524416) logdet (B,)
//             [524416,8913024) hist_jac (D,N,16)
#define SLOPE 0.2f
#define S 68              // smem row stride (floats); k*S stays 16B-aligned

#define OFF_X   0          // [17][S]  layer-0 inputs (k-major)
#define OFF_A   1156       // [64][S]  ping
#define OFF_B   5508       // [64][S]  pong
#define OFF_W   9860       // [64][S]  current weight tile (contraction-major)
#define OFF_OUT 14212      // [4][64]  per-tys partial head sums
#define OFF_J   14468      // [32]
#define OFF_SB0 14500
#define OFF_SB1 14564
#define OFF_SB2 14628
#define OFF_SWO 14692
#define SMEM_FLOATS 14756
#define SMEM_BYTES  (SMEM_FLOATS * 4)

typedef unsigned long long u64;
typedef unsigned int u32;

__device__ float g_partials[8192];   // [d][tile]

__device__ __forceinline__ u64 ffma2(u64 a, u64 b, u64 c) {
    u64 d; asm("fma.rn.f32x2 %0, %1, %2, %3;" : "=l"(d) : "l"(a), "l"(b), "l"(c)); return d;
}
__device__ __forceinline__ u64 pack2(float x, float y) {
    u64 r; asm("mov.b64 %0, {%1, %2};" : "=l"(r) : "f"(x), "f"(y)); return r;
}
__device__ __forceinline__ float2 unpk(u64 v) {
    float2 r; asm("mov.b64 {%0, %1}, %2;" : "=f"(r.x), "=f"(r.y) : "l"(v)); return r;
}
__device__ __forceinline__ float lk(float v) { return v > 0.f ? v : v * SLOPE; }
__device__ __forceinline__ float mb(u32 m, int b) { return ((m >> b) & 1u) ? 1.f : SLOPE; }

// 16 outputs (8 packed pairs, lanes = outputs) x 2 samples per thread.
// acc[p*2+j]: pair p (outs tys*16+2p, +2p+1), sample txs*2+j.
__device__ __forceinline__ void gemm16x2(const float* __restrict__ A,
                                         const float* __restrict__ Wc,
                                         int K, int txs, int tys, u64* acc) {
    const float* ap = A + txs * 2;
    const float* wp = Wc + tys * 16;
#pragma unroll 4
    for (int k = 0; k < K; ++k) {
        float2 a = *(const float2*)(ap + k * S);
        ulonglong2 w01 = *(const ulonglong2*)(wp + k * S);
        ulonglong2 w23 = *(const ulonglong2*)(wp + k * S + 4);
        ulonglong2 w45 = *(const ulonglong2*)(wp + k * S + 8);
        ulonglong2 w67 = *(const ulonglong2*)(wp + k * S + 12);
        u64 a0 = pack2(a.x, a.x), a1 = pack2(a.y, a.y);
        acc[0]  = ffma2(w01.x, a0, acc[0]);   acc[1]  = ffma2(w01.x, a1, acc[1]);
        acc[2]  = ffma2(w01.y, a0, acc[2]);   acc[3]  = ffma2(w01.y, a1, acc[3]);
        acc[4]  = ffma2(w23.x, a0, acc[4]);   acc[5]  = ffma2(w23.x, a1, acc[5]);
        acc[6]  = ffma2(w23.y, a0, acc[6]);   acc[7]  = ffma2(w23.y, a1, acc[7]);
        acc[8]  = ffma2(w45.x, a0, acc[8]);   acc[9]  = ffma2(w45.x, a1, acc[9]);
        acc[10] = ffma2(w45.y, a0, acc[10]);  acc[11] = ffma2(w45.y, a1, acc[11]);
        acc[12] = ffma2(w67.x, a0, acc[12]);  acc[13] = ffma2(w67.x, a1, acc[13]);
        acc[14] = ffma2(w67.y, a0, acc[14]);  acc[15] = ffma2(w67.y, a1, acc[15]);
    }
}

// stage 64x64 row-major weights -> transposed [k][h] (contraction-major for forward)
__device__ __forceinline__ void stage_T(float* sm, const float* __restrict__ Wsrc, int tid) {
    const float4* src = (const float4*)Wsrc;
#pragma unroll
    for (int q = 0; q < 8; ++q) {
        int i4 = q * 128 + tid;
        float4 v = src[i4];
        int h = i4 >> 4, c = (i4 & 15) * 4;
        float* dst = sm + OFF_W + h;
        dst[(c + 0) * S] = v.x;
        dst[(c + 1) * S] = v.y;
        dst[(c + 2) * S] = v.z;
        dst[(c + 3) * S] = v.w;
    }
}
// stage 64x64 row-major weights as-is [h][k] (contraction-major for backward)
__device__ __forceinline__ void stage_R(float* sm, const float* __restrict__ Wsrc, int tid) {
    const float4* src = (const float4*)Wsrc;
#pragma unroll
    for (int q = 0; q < 8; ++q) {
        int i4 = q * 128 + tid;
        float4 v = src[i4];
        *(float4*)(sm + OFF_W + (i4 >> 4) * S + (i4 & 15) * 4) = v;
    }
}

__global__ void __launch_bounds__(128, 3)
mlp_tile_kernel(const float* __restrict__ x,
                const float* __restrict__ W0, const float* __restrict__ b0,
                const float* __restrict__ W1, const float* __restrict__ b1,
                const float* __restrict__ W2, const float* __restrict__ b2,
                const float* __restrict__ Wo, const float* __restrict__ bo,
                float* __restrict__ out)
{
    extern __shared__ float sm[];
    const int tid  = threadIdx.x;
    const int txs  = tid & 31;      // 2 samples
    const int tys  = tid >> 5;      // 16 outputs
    const int tile = blockIdx.x;
    const int d    = blockIdx.y;

    // ---------------- stage inputs, W0^T, biases ----------------
    {
        const int s = tid & 63, half = tid >> 6;
        const int n = tile * 64 + s;
        const float* xb = x + (size_t)((n >> 9) * 514 + (n & 511)) * 8;
        float4 v0 = *(const float4*)(xb + half * 8);
        float4 v1 = *(const float4*)(xb + half * 8 + 4);
        float* dst = sm + OFF_X + s;
        dst[(half * 8 + 0) * S] = v0.x;  dst[(half * 8 + 1) * S] = v0.y;
        dst[(half * 8 + 2) * S] = v0.z;  dst[(half * 8 + 3) * S] = v0.w;
        dst[(half * 8 + 4) * S] = v1.x;  dst[(half * 8 + 5) * S] = v1.y;
        dst[(half * 8 + 6) * S] = v1.z;  dst[(half * 8 + 7) * S] = v1.w;
        if (half == 0) dst[16 * S] = xb[16 + d];
    }
    for (int i = tid; i < 1088; i += 128) {             // W0^T [k][h]
        int h = i / 17, k = i - 17 * h;
        sm[OFF_W + k * S + h] = W0[d * 1088 + i];
    }
    if (tid < 64) {
        sm[OFF_SB0 + tid] = b0[d * 64 + tid];
        sm[OFF_SB1 + tid] = b1[d * 64 + tid];
        sm[OFF_SB2 + tid] = b2[d * 64 + tid];
        sm[OFF_SWO + tid] = Wo[d * 64 + tid];
    }
    __syncthreads();

    u64 acc[16];
    u32 m0 = 0, m1 = 0;

    // ---------------- layer 0: X -> A ----------------
#pragma unroll
    for (int p = 0; p < 8; ++p) {
        u64 bp = *(const u64*)(sm + OFF_SB0 + tys * 16 + 2 * p);
        acc[2 * p] = bp; acc[2 * p + 1] = bp;
    }
    gemm16x2(sm + OFF_X, sm + OFF_W, 17, txs, tys, acc);
#pragma unroll
    for (int p = 0; p < 8; ++p) {
        float2 v0 = unpk(acc[2 * p]), v1 = unpk(acc[2 * p + 1]);
        m0 |= ((u32)(v0.x > 0.f) << (4 * p))     | ((u32)(v1.x > 0.f) << (4 * p + 1))
            | ((u32)(v0.y > 0.f) << (4 * p + 2)) | ((u32)(v1.y > 0.f) << (4 * p + 3));
        *(float2*)(sm + OFF_A + (tys * 16 + 2 * p) * S + txs * 2)     = make_float2(lk(v0.x), lk(v1.x));
        *(float2*)(sm + OFF_A + (tys * 16 + 2 * p + 1) * S + txs * 2) = make_float2(lk(v0.y), lk(v1.y));
    }
    __syncthreads();

    // ---------------- layer 1: A -> B ----------------
    stage_T(sm, W1 + d * 4096, tid);
    __syncthreads();
#pragma unroll
    for (int p = 0; p < 8; ++p) {
        u64 bp = *(const u64*)(sm + OFF_SB1 + tys * 16 + 2 * p);
        acc[2 * p] = bp; acc[2 * p + 1] = bp;
    }
    gemm16x2(sm + OFF_A, sm + OFF_W, 64, txs, tys, acc);
#pragma unroll
    for (int p = 0; p < 8; ++p) {
        float2 v0 = unpk(acc[2 * p]), v1 = unpk(acc[2 * p + 1]);
        m1 |= ((u32)(v0.x > 0.f) << (4 * p))     | ((u32)(v1.x > 0.f) << (4 * p + 1))
            | ((u32)(v0.y > 0.f) << (4 * p + 2)) | ((u32)(v1.y > 0.f) << (4 * p + 3));
        *(float2*)(sm + OFF_B + (tys * 16 + 2 * p) * S + txs * 2)     = make_float2(lk(v0.x), lk(v1.x));
        *(float2*)(sm + OFF_B + (tys * 16 + 2 * p + 1) * S + txs * 2) = make_float2(lk(v0.y), lk(v1.y));
    }
    __syncthreads();

    // ---------------- layer 2 + head: B -> g in A ----------------
    stage_T(sm, W2 + d * 4096, tid);
    __syncthreads();
#pragma unroll
    for (int p = 0; p < 8; ++p) {
        u64 bp = *(const u64*)(sm + OFF_SB2 + tys * 16 + 2 * p);
        acc[2 * p] = bp; acc[2 * p + 1] = bp;
    }
    gemm16x2(sm + OFF_B, sm + OFF_W, 64, txs, tys, acc);
    {
        float2 osum = make_float2(0.f, 0.f);
#pragma unroll
        for (int p = 0; p < 8; ++p) {
            float wl = sm[OFF_SWO + tys * 16 + 2 * p];
            float wh = sm[OFF_SWO + tys * 16 + 2 * p + 1];
            float2 v0 = unpk(acc[2 * p]), v1 = unpk(acc[2 * p + 1]);
            float g00 = wl * (v0.x > 0.f ? 1.f : SLOPE);  // out 2p, sample 0
            float g01 = wl * (v1.x > 0.f ? 1.f : SLOPE);  // out 2p, sample 1
            float g10 = wh * (v0.y > 0.f ? 1.f : SLOPE);  // out 2p+1, sample 0
            float g11 = wh * (v1.y > 0.f ? 1.f : SLOPE);
            osum.x = fmaf(g00, v0.x, fmaf(g10, v0.y, osum.x));
            osum.y = fmaf(g01, v1.x, fmaf(g11, v1.y, osum.y));
            *(float2*)(sm + OFF_A + (tys * 16 + 2 * p) * S + txs * 2)     = make_float2(g00, g01);
            *(float2*)(sm + OFF_A + (tys * 16 + 2 * p + 1) * S + txs * 2) = make_float2(g10, g11);
        }
        *(float2*)(sm + OFF_OUT + tys * 64 + txs * 2) = osum;
    }
    __syncthreads();

    // residual store + W2 row-major stage
    stage_R(sm, W2 + d * 4096, tid);
    if (tid < 64) {
        float r = bo[d];
#pragma unroll
        for (int q = 0; q < 4; ++q) r += sm[OFF_OUT + q * 64 + tid];
        out[(size_t)(tile * 64 + tid) * 8 + d] = r;
    }
    __syncthreads();

    // ---------------- bwd2: g2 = (g @ W2) * m1,  A -> B ----------------
#pragma unroll
    for (int i = 0; i < 16; ++i) acc[i] = 0ull;
    gemm16x2(sm + OFF_A, sm + OFF_W, 64, txs, tys, acc);
#pragma unroll
    for (int p = 0; p < 8; ++p) {
        float2 v0 = unpk(acc[2 * p]), v1 = unpk(acc[2 * p + 1]);
        *(float2*)(sm + OFF_B + (tys * 16 + 2 * p) * S + txs * 2) =
            make_float2(v0.x * mb(m1, 4 * p), v1.x * mb(m1, 4 * p + 1));
        *(float2*)(sm + OFF_B + (tys * 16 + 2 * p + 1) * S + txs * 2) =
            make_float2(v0.y * mb(m1, 4 * p + 2), v1.y * mb(m1, 4 * p + 3));
    }
    __syncthreads();

    // ---------------- bwd1: g1 = (g2 @ W1) * m0,  B -> A ----------------
    stage_R(sm, W1 + d * 4096, tid);
    __syncthreads();
#pragma unroll
    for (int i = 0; i < 16; ++i) acc[i] = 0ull;
    gemm16x2(sm + OFF_B, sm + OFF_W, 64, txs, tys, acc);
#pragma unroll
    for (int p = 0; p < 8; ++p) {
        float2 v0 = unpk(acc[2 * p]), v1 = unpk(acc[2 * p + 1]);
        *(float2*)(sm + OFF_A + (tys * 16 + 2 * p) * S + txs * 2) =
            make_float2(v0.x * mb(m0, 4 * p), v1.x * mb(m0, 4 * p + 1));
        *(float2*)(sm + OFF_A + (tys * 16 + 2 * p + 1) * S + txs * 2) =
            make_float2(v0.y * mb(m0, 4 * p + 2), v1.y * mb(m0, 4 * p + 3));
    }
    __syncthreads();

    // ---------------- jac = g1 @ W0 (24 padded outs) ----------------
    for (int i = tid; i < 64 * 24; i += 128) {
        int h = i / 24, c = i - 24 * h;
        sm[OFF_W + h * S + c] = (c < 17) ? W0[d * 1088 + h * 17 + c] : 0.f;
    }
    __syncthreads();
    {
        const int tyj = tid >> 5;      // 0..3 (3 used)
        const int txj = tid & 31;      // 2 samples
        if (tyj < 3) {
            u64 a2[8];                 // 4 out-pairs x 2 samples
#pragma unroll
            for (int i = 0; i < 8; ++i) a2[i] = 0ull;
            const float* ap = sm + OFF_A + txj * 2;
            const float* wp = sm + OFF_W + tyj * 8;
#pragma unroll 4
            for (int k = 0; k < 64; ++k) {
                float2 a = *(const float2*)(ap + k * S);
                ulonglong2 wA = *(const ulonglong2*)(wp + k * S);
                ulonglong2 wB = *(const ulonglong2*)(wp + k * S + 4);
                u64 a0 = pack2(a.x, a.x), a1 = pack2(a.y, a.y);
                a2[0] = ffma2(wA.x, a0, a2[0]);  a2[1] = ffma2(wA.x, a1, a2[1]);
                a2[2] = ffma2(wA.y, a0, a2[2]);  a2[3] = ffma2(wA.y, a1, a2[3]);
                a2[4] = ffma2(wB.x, a0, a2[4]);  a2[5] = ffma2(wB.x, a1, a2[5]);
                a2[6] = ffma2(wB.y, a0, a2[6]);  a2[7] = ffma2(wB.y, a1, a2[7]);
            }
            if (tyj < 2) {
#pragma unroll
                for (int j = 0; j < 2; ++j) {
                    int n = tile * 64 + txj * 2 + j;
                    float2 p0 = unpk(a2[0 + j]), p1 = unpk(a2[2 + j]);
                    float2 p2 = unpk(a2[4 + j]), p3 = unpk(a2[6 + j]);
                    float* dst = out + 524416 + ((size_t)d * 65536 + n) * 16 + tyj * 8;
                    *(float4*)dst       = make_float4(p0.x, p0.y, p1.x, p1.y);
                    *(float4*)(dst + 4) = make_float4(p2.x, p2.y, p3.x, p3.y);
                }
            } else {
                float2 j0 = unpk(a2[0]);   // out 16 = lo of pair 0
                float2 j1 = unpk(a2[1]);
                sm[OFF_J + txj] = logf(fabsf(j0.x)) + logf(fabsf(j1.x));
            }
        }
    }
    __syncthreads();
    if (tid == 0) {
        float sj = 0.f;
#pragma unroll
        for (int q = 0; q < 32; ++q) sj += sm[OFF_J + q];
        g_partials[d * 1024 + tile] = sj;
    }
}

__global__ void logdet_reduce_kernel(float* __restrict__ out) {
    const int b = threadIdx.x;    // 128 threads
    float s = 0.f;
#pragma unroll
    for (int d = 0; d < 8; ++d)
#pragma unroll
        for (int q = 0; q < 8; ++q)
            s += g_partials[d * 1024 + b * 8 + q];
    out[524288 + b] = s;
}

extern "C" void kernel_launch(void* const* d_in, const int* in_sizes, int n_in,
                              void* d_out, int out_size) {
    const float* x  = (const float*)d_in[0];
    const float* W0 = (const float*)d_in[1];
    const float* b0 = (const float*)d_in[2];
    const float* W1 = (const float*)d_in[3];
    const float* b1 = (const float*)d_in[4];
    const float* W2 = (const float*)d_in[5];
    const float* b2 = (const float*)d_in[6];
    const float* Wo = (const float*)d_in[7];
    const float* bo = (const float*)d_in[8];
    float* out = (float*)d_out;

    cudaFuncSetAttribute(mlp_tile_kernel,
                         cudaFuncAttributeMaxDynamicSharedMemorySize, SMEM_BYTES);
    dim3 grid(1024, 8);
    mlp_tile_kernel<<<grid, 128, SMEM_BYTES>>>(x, W0, b0, W1, b1, W2, b2, Wo, bo, out);
    logdet_reduce_kernel<<<1, 128>>>(out);
}

// round 7
// speedup vs baseline: 1.6057x; 1.0642x over previous
#include <cuda_runtime.h>
#include <math.h>

// Fixed problem: B=128, T=514, D=8, H=64, L=2, IN=17, W=512, N=65536
// out layout: [0,524288) residuals (B,W,D) | [524288,524416) logdet (B,)
//             [524416,8913024) hist_jac (D,N,16)
#define SLOPE 0.2f
#define SACT 132          // activation row stride (128 samples + pad)
#define SW   68           // weight row stride (64 + pad)

// smem float offsets
#define OFF_OUT 0          // [4][128] partial head sums (reuses X region)
#define OFF_J   512        // [64] logdet partials      (reuses X region)
#define OFF_X   0          // [17][SACT] layer-0 inputs (freed after layer 0)
#define OFF_A   2244       // [64][SACT] ping
#define OFF_B   10692      // [64][SACT] pong
#define OFF_WA  19140      // [64][SW] weight buffer A
#define OFF_WB  23492      // [64][SW] weight buffer B
#define OFF_SB0 27844
#define OFF_SB1 27908
#define OFF_SB2 27972
#define OFF_SWO 28036
#define SMEM_FLOATS 28100
#define SMEM_BYTES  (SMEM_FLOATS * 4)

typedef unsigned long long u64;
typedef unsigned int u32;

__device__ float g_partials[4096];   // [d][tile] (8 x 512)

__device__ __forceinline__ u64 ffma2(u64 a, u64 b, u64 c) {
    u64 d; asm("fma.rn.f32x2 %0, %1, %2, %3;" : "=l"(d) : "l"(a), "l"(b), "l"(c)); return d;
}
__device__ __forceinline__ u64 pack2(float x, float y) {
    u64 r; asm("mov.b64 %0, {%1, %2};" : "=l"(r) : "f"(x), "f"(y)); return r;
}
__device__ __forceinline__ float2 unpk(u64 v) {
    float2 r; asm("mov.b64 {%0, %1}, %2;" : "=f"(r.x), "=f"(r.y) : "l"(v)); return r;
}
__device__ __forceinline__ float lk(float v) { return v > 0.f ? v : v * SLOPE; }
__device__ __forceinline__ float mb(u32 m, int b) { return ((m >> b) & 1u) ? 1.f : SLOPE; }

// 16 outputs (8 packed pairs) x 2 samples per thread.
// acc[2p+j]: pair p (outs tys*16+2p, +2p+1), sample txs*2+j.
__device__ __forceinline__ void gemm16x2(const float* __restrict__ A,
                                         const float* __restrict__ Wc,
                                         int K, int txs, int tys, u64* acc) {
    const float* ap = A + txs * 2;
    const float* wp = Wc + tys * 16;
#pragma unroll 4
    for (int k = 0; k < K; ++k) {
        float2 a = *(const float2*)(ap + k * SACT);
        ulonglong2 w01 = *(const ulonglong2*)(wp + k * SW);
        ulonglong2 w23 = *(const ulonglong2*)(wp + k * SW + 4);
        ulonglong2 w45 = *(const ulonglong2*)(wp + k * SW + 8);
        ulonglong2 w67 = *(const ulonglong2*)(wp + k * SW + 12);
        u64 a0 = pack2(a.x, a.x), a1 = pack2(a.y, a.y);
        acc[0]  = ffma2(w01.x, a0, acc[0]);   acc[1]  = ffma2(w01.x, a1, acc[1]);
        acc[2]  = ffma2(w01.y, a0, acc[2]);   acc[3]  = ffma2(w01.y, a1, acc[3]);
        acc[4]  = ffma2(w23.x, a0, acc[4]);   acc[5]  = ffma2(w23.x, a1, acc[5]);
        acc[6]  = ffma2(w23.y, a0, acc[6]);   acc[7]  = ffma2(w23.y, a1, acc[7]);
        acc[8]  = ffma2(w45.x, a0, acc[8]);   acc[9]  = ffma2(w45.x, a1, acc[9]);
        acc[10] = ffma2(w45.y, a0, acc[10]);  acc[11] = ffma2(w45.y, a1, acc[11]);
        acc[12] = ffma2(w67.x, a0, acc[12]);  acc[13] = ffma2(w67.x, a1, acc[13]);
        acc[14] = ffma2(w67.y, a0, acc[14]);  acc[15] = ffma2(w67.y, a1, acc[15]);
    }
}

// --- weight prefetch (gmem->regs) and store (regs->smem) helpers ---
// Transposed ([k][h]): h-major loads so STS lanes hit consecutive banks.
#define PREF_T(SRC)                                                        \
    _Pragma("unroll")                                                      \
    for (int q = 0; q < 4; ++q) {                                          \
        int i4 = q * 256 + tid;                                            \
        pre[q] = ((const float4*)(SRC))[(i4 & 63) * 16 + (i4 >> 6)];       \
    }
#define STS_T(DST)                                                         \
    _Pragma("unroll")                                                      \
    for (int q = 0; q < 4; ++q) {                                          \
        int i4 = q * 256 + tid;                                            \
        int h = i4 & 63, cg = i4 >> 6;                                     \
        float* dp = sm + (DST) + h;                                        \
        dp[(4 * cg + 0) * SW] = pre[q].x;                                  \
        dp[(4 * cg + 1) * SW] = pre[q].y;                                  \
        dp[(4 * cg + 2) * SW] = pre[q].z;                                  \
        dp[(4 * cg + 3) * SW] = pre[q].w;                                  \
    }
// Row-major ([h][k]): coalesced LDG.128, conflict-free STS.128.
#define PREF_R(SRC)                                                        \
    _Pragma("unroll")                                                      \
    for (int q = 0; q < 4; ++q) pre[q] = ((const float4*)(SRC))[q * 256 + tid];
#define STS_R(DST)                                                         \
    _Pragma("unroll")                                                      \
    for (int q = 0; q < 4; ++q) {                                          \
        int i4 = q * 256 + tid;                                            \
        *(float4*)(sm + (DST) + (i4 >> 4) * SW + (i4 & 15) * 4) = pre[q];  \
    }

__global__ void __launch_bounds__(256, 2)
mlp_tile_kernel(const float* __restrict__ x,
                const float* __restrict__ W0, const float* __restrict__ b0,
                const float* __restrict__ W1, const float* __restrict__ b1,
                const float* __restrict__ W2, const float* __restrict__ b2,
                const float* __restrict__ Wo, const float* __restrict__ bo,
                float* __restrict__ out)
{
    extern __shared__ float sm[];
    const int tid  = threadIdx.x;
    const int txs  = tid & 63;      // 2 samples
    const int tys  = tid >> 6;      // 16 outputs
    const int tile = blockIdx.x;    // 0..511 (128 samples)
    const int d    = blockIdx.y;

    const float bo_d = bo[d];

    // -------- phase 1: stage X, W0^T -> WA, biases --------
    {
        const int s = tid & 127, half = tid >> 7;
        const int n = tile * 128 + s;
        const float* xb = x + (size_t)((n >> 9) * 514 + (n & 511)) * 8;
        float4 v0 = *(const float4*)(xb + half * 8);
        float4 v1 = *(const float4*)(xb + half * 8 + 4);
        float* dst = sm + OFF_X + s;
        dst[(half * 8 + 0) * SACT] = v0.x;  dst[(half * 8 + 1) * SACT] = v0.y;
        dst[(half * 8 + 2) * SACT] = v0.z;  dst[(half * 8 + 3) * SACT] = v0.w;
        dst[(half * 8 + 4) * SACT] = v1.x;  dst[(half * 8 + 5) * SACT] = v1.y;
        dst[(half * 8 + 6) * SACT] = v1.z;  dst[(half * 8 + 7) * SACT] = v1.w;
        if (half == 0) dst[16 * SACT] = xb[16 + d];
    }
    for (int i = tid; i < 1088; i += 256) {         // W0^T [k][h]
        int h = i / 17, k = i - 17 * h;
        sm[OFF_WA + k * SW + h] = W0[d * 1088 + i];
    }
    if (tid < 64) {
        sm[OFF_SB0 + tid] = b0[d * 64 + tid];
        sm[OFF_SB1 + tid] = b1[d * 64 + tid];
        sm[OFF_SB2 + tid] = b2[d * 64 + tid];
        sm[OFF_SWO + tid] = Wo[d * 64 + tid];
    }
    __syncthreads();

    u64 acc[16];
    u32 m0 = 0, m1 = 0;
    float4 pre[4];

    // -------- phase 2: L0 (X, WA) -> A; prefetch W1^T -> WB --------
    PREF_T(W1 + d * 4096);
#pragma unroll
    for (int p = 0; p < 8; ++p) {
        u64 bp = *(const u64*)(sm + OFF_SB0 + tys * 16 + 2 * p);
        acc[2 * p] = bp; acc[2 * p + 1] = bp;
    }
    gemm16x2(sm + OFF_X, sm + OFF_WA, 17, txs, tys, acc);
#pragma unroll
    for (int p = 0; p < 8; ++p) {
        float2 v0 = unpk(acc[2 * p]), v1 = unpk(acc[2 * p + 1]);
        m0 |= ((u32)(v0.x > 0.f) << (4 * p))     | ((u32)(v1.x > 0.f) << (4 * p + 1))
            | ((u32)(v0.y > 0.f) << (4 * p + 2)) | ((u32)(v1.y > 0.f) << (4 * p + 3));
        *(float2*)(sm + OFF_A + (tys * 16 + 2 * p) * SACT + txs * 2)     = make_float2(lk(v0.x), lk(v1.x));
        *(float2*)(sm + OFF_A + (tys * 16 + 2 * p + 1) * SACT + txs * 2) = make_float2(lk(v0.y), lk(v1.y));
    }
    STS_T(OFF_WB);
    __syncthreads();

    // -------- phase 3: L1 (A, WB) -> B; prefetch W2^T -> WA --------
    PREF_T(W2 + d * 4096);
#pragma unroll
    for (int p = 0; p < 8; ++p) {
        u64 bp = *(const u64*)(sm + OFF_SB1 + tys * 16 + 2 * p);
        acc[2 * p] = bp; acc[2 * p + 1] = bp;
    }
    gemm16x2(sm + OFF_A, sm + OFF_WB, 64, txs, tys, acc);
#pragma unroll
    for (int p = 0; p < 8; ++p) {
        float2 v0 = unpk(acc[2 * p]), v1 = unpk(acc[2 * p + 1]);
        m1 |= ((u32)(v0.x > 0.f) << (4 * p))     | ((u32)(v1.x > 0.f) << (4 * p + 1))
            | ((u32)(v0.y > 0.f) << (4 * p + 2)) | ((u32)(v1.y > 0.f) << (4 * p + 3));
        *(float2*)(sm + OFF_B + (tys * 16 + 2 * p) * SACT + txs * 2)     = make_float2(lk(v0.x), lk(v1.x));
        *(float2*)(sm + OFF_B + (tys * 16 + 2 * p + 1) * SACT + txs * 2) = make_float2(lk(v0.y), lk(v1.y));
    }
    STS_T(OFF_WA);
    __syncthreads();

    // -------- phase 4: L2 + head (B, WA) -> g in A, osum -> OUT; prefetch W2 row -> WB --------
    PREF_R(W2 + d * 4096);
#pragma unroll
    for (int p = 0; p < 8; ++p) {
        u64 bp = *(const u64*)(sm + OFF_SB2 + tys * 16 + 2 * p);
        acc[2 * p] = bp; acc[2 * p + 1] = bp;
    }
    gemm16x2(sm + OFF_B, sm + OFF_WA, 64, txs, tys, acc);
    {
        float2 osum = make_float2(0.f, 0.f);
#pragma unroll
        for (int p = 0; p < 8; ++p) {
            float wl = sm[OFF_SWO + tys * 16 + 2 * p];
            float wh = sm[OFF_SWO + tys * 16 + 2 * p + 1];
            float2 v0 = unpk(acc[2 * p]), v1 = unpk(acc[2 * p + 1]);
            float g00 = wl * (v0.x > 0.f ? 1.f : SLOPE);
            float g01 = wl * (v1.x > 0.f ? 1.f : SLOPE);
            float g10 = wh * (v0.y > 0.f ? 1.f : SLOPE);
            float g11 = wh * (v1.y > 0.f ? 1.f : SLOPE);
            osum.x = fmaf(g00, v0.x, fmaf(g10, v0.y, osum.x));
            osum.y = fmaf(g01, v1.x, fmaf(g11, v1.y, osum.y));
            *(float2*)(sm + OFF_A + (tys * 16 + 2 * p) * SACT + txs * 2)     = make_float2(g00, g01);
            *(float2*)(sm + OFF_A + (tys * 16 + 2 * p + 1) * SACT + txs * 2) = make_float2(g10, g11);
        }
        *(float2*)(sm + OFF_OUT + tys * 128 + txs * 2) = osum;
    }
    STS_R(OFF_WB);
    __syncthreads();

    // -------- phase 5: residuals; bwd2 (A, WB)*m1 -> B; prefetch W1 row -> WA --------
    if (tid < 128) {
        float r = bo_d;
#pragma unroll
        for (int q = 0; q < 4; ++q) r += sm[OFF_OUT + q * 128 + tid];
        out[(size_t)(tile * 128 + tid) * 8 + d] = r;
    }
    PREF_R(W1 + d * 4096);
#pragma unroll
    for (int i = 0; i < 16; ++i) acc[i] = 0ull;
    gemm16x2(sm + OFF_A, sm + OFF_WB, 64, txs, tys, acc);
#pragma unroll
    for (int p = 0; p < 8; ++p) {
        float2 v0 = unpk(acc[2 * p]), v1 = unpk(acc[2 * p + 1]);
        *(float2*)(sm + OFF_B + (tys * 16 + 2 * p) * SACT + txs * 2) =
            make_float2(v0.x * mb(m1, 4 * p), v1.x * mb(m1, 4 * p + 1));
        *(float2*)(sm + OFF_B + (tys * 16 + 2 * p + 1) * SACT + txs * 2) =
            make_float2(v0.y * mb(m1, 4 * p + 2), v1.y * mb(m1, 4 * p + 3));
    }
    STS_R(OFF_WA);
    __syncthreads();

    // -------- phase 6: bwd1 (B, WA)*m0 -> A; prefetch W0 row (24-pad) -> WB --------
    float w0pre[5];
#pragma unroll
    for (int q = 0; q < 5; ++q) {
        int i = q * 256 + tid;
        w0pre[q] = (i < 1088) ? W0[d * 1088 + i] : 0.f;
    }
#pragma unroll
    for (int i = 0; i < 16; ++i) acc[i] = 0ull;
    gemm16x2(sm + OFF_B, sm + OFF_WA, 64, txs, tys, acc);
#pragma unroll
    for (int p = 0; p < 8; ++p) {
        float2 v0 = unpk(acc[2 * p]), v1 = unpk(acc[2 * p + 1]);
        *(float2*)(sm + OFF_A + (tys * 16 + 2 * p) * SACT + txs * 2) =
            make_float2(v0.x * mb(m0, 4 * p), v1.x * mb(m0, 4 * p + 1));
        *(float2*)(sm + OFF_A + (tys * 16 + 2 * p + 1) * SACT + txs * 2) =
            make_float2(v0.y * mb(m0, 4 * p + 2), v1.y * mb(m0, 4 * p + 3));
    }
#pragma unroll
    for (int q = 0; q < 5; ++q) {
        int i = q * 256 + tid;
        if (i < 1088) {
            int h = i / 17, c = i - 17 * h;
            sm[OFF_WB + h * SW + c] = w0pre[q];
        }
    }
    for (int i = tid; i < 448; i += 256) {          // zero pad cols 17..23
        int h = i / 7, c = 17 + (i - 7 * h);
        sm[OFF_WB + h * SW + c] = 0.f;
    }
    __syncthreads();

    // -------- phase 7: jac = g1 @ W0 (24 padded outs) --------
    {
        const int tyj = tid >> 6;      // 0..3 (3 used)
        const int txj = tid & 63;      // 2 samples
        if (tyj < 3) {
            u64 a2[8];                 // 4 out-pairs x 2 samples
#pragma unroll
            for (int i = 0; i < 8; ++i) a2[i] = 0ull;
            const float* ap = sm + OFF_A + txj * 2;
            const float* wp = sm + OFF_WB + tyj * 8;
#pragma unroll 4
            for (int k = 0; k < 64; ++k) {
                float2 a = *(const float2*)(ap + k * SACT);
                ulonglong2 wA = *(const ulonglong2*)(wp + k * SW);
                ulonglong2 wB = *(const ulonglong2*)(wp + k * SW + 4);
                u64 a0 = pack2(a.x, a.x), a1 = pack2(a.y, a.y);
                a2[0] = ffma2(wA.x, a0, a2[0]);  a2[1] = ffma2(wA.x, a1, a2[1]);
                a2[2] = ffma2(wA.y, a0, a2[2]);  a2[3] = ffma2(wA.y, a1, a2[3]);
                a2[4] = ffma2(wB.x, a0, a2[4]);  a2[5] = ffma2(wB.x, a1, a2[5]);
                a2[6] = ffma2(wB.y, a0, a2[6]);  a2[7] = ffma2(wB.y, a1, a2[7]);
            }
            if (tyj < 2) {
#pragma unroll
                for (int j = 0; j < 2; ++j) {
                    int n = tile * 128 + txj * 2 + j;
                    float2 p0 = unpk(a2[0 + j]), p1 = unpk(a2[2 + j]);
                    float2 p2 = unpk(a2[4 + j]), p3 = unpk(a2[6 + j]);
                    float* dst = out + 524416 + ((size_t)d * 65536 + n) * 16 + tyj * 8;
                    *(float4*)dst       = make_float4(p0.x, p0.y, p1.x, p1.y);
                    *(float4*)(dst + 4) = make_float4(p2.x, p2.y, p3.x, p3.y);
                }
            } else {
                float2 j0 = unpk(a2[0]);   // out 16 = lo of pair 0
                float2 j1 = unpk(a2[1]);
                sm[OFF_J + txj] = logf(fabsf(j0.x)) + logf(fabsf(j1.x));
            }
        }
    }
    __syncthreads();
    if (tid == 0) {
        float sj = 0.f;
#pragma unroll
        for (int q = 0; q < 64; ++q) sj += sm[OFF_J + q];
        g_partials[d * 512 + tile] = sj;
    }
}

// logdet[b] = fixed-order sum over d(8) x 4 tiles of batch b
__global__ void logdet_reduce_kernel(float* __restrict__ out) {
    const int b = threadIdx.x;    // 128 threads
    float s = 0.f;
#pragma unroll
    for (int d = 0; d < 8; ++d)
#pragma unroll
        for (int q = 0; q < 4; ++q)
            s += g_partials[d * 512 + b * 4 + q];
    out[524288 + b] = s;
}

extern "C" void kernel_launch(void* const* d_in, const int* in_sizes, int n_in,
                              void* d_out, int out_size) {
    const float* x  = (const float*)d_in[0];
    const float* W0 = (const float*)d_in[1];
    const float* b0 = (const float*)d_in[2];
    const float* W1 = (const float*)d_in[3];
    const float* b1 = (const float*)d_in[4];
    const float* W2 = (const float*)d_in[5];
    const float* b2 = (const float*)d_in[6];
    const float* Wo = (const float*)d_in[7];
    const float* bo = (const float*)d_in[8];
    float* out = (float*)d_out;

    cudaFuncSetAttribute(mlp_tile_kernel,
                         cudaFuncAttributeMaxDynamicSharedMemorySize, SMEM_BYTES);
    dim3 grid(512, 8);
    mlp_tile_kernel<<<grid, 256, SMEM_BYTES>>>(x, W0, b0, W1, b1, W2, b2, Wo, bo, out);
    logdet_reduce_kernel<<<1, 128>>>(out);
}

// round 8
// speedup vs baseline: 1.6824x; 1.0477x over previous
#include <cuda_runtime.h>
#include <math.h>

// Fixed problem: B=128, T=514, D=8, H=64, L=2, IN=17, W=512, N=65536
// out layout: [0,524288) residuals (B,W,D) | [524288,524416) logdet (B,)
//             [524416,8913024) hist_jac (D,N,16)
#define SLOPE 0.2f
#define SACT 132          // activation row stride (128 samples + pad)
#define SW   68           // weight row stride (64 + pad)

// smem float offsets
#define OFF_OUT 0          // [4][128] partial head sums (reuses X region)
#define OFF_J   512        // [64] logdet partials      (reuses X region)
#define OFF_X   0          // [17][SACT] layer-0 inputs (freed after layer 0)
#define OFF_A   2244       // [64][SACT] ping
#define OFF_B   10692      // [64][SACT] pong
#define OFF_WA  19140      // [64][SW] weight buffer A
#define OFF_WB  23492      // [64][SW] weight buffer B
#define OFF_SB0 27844
#define OFF_SB1 27908
#define OFF_SB2 27972
#define OFF_SWO 28036
#define SMEM_FLOATS 28100
#define SMEM_BYTES  (SMEM_FLOATS * 4)

typedef unsigned long long u64;
typedef unsigned int u32;

__device__ float g_partials[4096];   // [d][tile] (8 x 512)

__device__ __forceinline__ u64 ffma2(u64 a, u64 b, u64 c) {
    u64 d; asm("fma.rn.f32x2 %0, %1, %2, %3;" : "=l"(d) : "l"(a), "l"(b), "l"(c)); return d;
}
__device__ __forceinline__ u64 pack2(float x, float y) {
    u64 r; asm("mov.b64 %0, {%1, %2};" : "=l"(r) : "f"(x), "f"(y)); return r;
}
__device__ __forceinline__ float2 unpk(u64 v) {
    float2 r; asm("mov.b64 {%0, %1}, %2;" : "=f"(r.x), "=f"(r.y) : "l"(v)); return r;
}
__device__ __forceinline__ float lk(float v) { return v > 0.f ? v : v * SLOPE; }
__device__ __forceinline__ float mb(u32 m, int b) { return ((m >> b) & 1u) ? 1.f : SLOPE; }

// 16 outputs (8 packed pairs) x 2 samples per thread.
__device__ __forceinline__ void gemm16x2(const float* __restrict__ A,
                                         const float* __restrict__ Wc,
                                         int K, int txs, int tys, u64* acc) {
    const float* ap = A + txs * 2;
    const float* wp = Wc + tys * 16;
#pragma unroll 4
    for (int k = 0; k < K; ++k) {
        float2 a = *(const float2*)(ap + k * SACT);
        ulonglong2 w01 = *(const ulonglong2*)(wp + k * SW);
        ulonglong2 w23 = *(const ulonglong2*)(wp + k * SW + 4);
        ulonglong2 w45 = *(const ulonglong2*)(wp + k * SW + 8);
        ulonglong2 w67 = *(const ulonglong2*)(wp + k * SW + 12);
        u64 a0 = pack2(a.x, a.x), a1 = pack2(a.y, a.y);
        acc[0]  = ffma2(w01.x, a0, acc[0]);   acc[1]  = ffma2(w01.x, a1, acc[1]);
        acc[2]  = ffma2(w01.y, a0, acc[2]);   acc[3]  = ffma2(w01.y, a1, acc[3]);
        acc[4]  = ffma2(w23.x, a0, acc[4]);   acc[5]  = ffma2(w23.x, a1, acc[5]);
        acc[6]  = ffma2(w23.y, a0, acc[6]);   acc[7]  = ffma2(w23.y, a1, acc[7]);
        acc[8]  = ffma2(w45.x, a0, acc[8]);   acc[9]  = ffma2(w45.x, a1, acc[9]);
        acc[10] = ffma2(w45.y, a0, acc[10]);  acc[11] = ffma2(w45.y, a1, acc[11]);
        acc[12] = ffma2(w67.x, a0, acc[12]);  acc[13] = ffma2(w67.x, a1, acc[13]);
        acc[14] = ffma2(w67.y, a0, acc[14]);  acc[15] = ffma2(w67.y, a1, acc[15]);
    }
}

// Coalesced row-major prefetch: thread gets W[h][4c..4c+3], h=i4>>4, c=i4&15.
#define PREF_R(SRC)                                                        \
    _Pragma("unroll")                                                      \
    for (int q = 0; q < 4; ++q) pre[q] = ((const float4*)(SRC))[q * 256 + tid];
// Store as-is [h][k] (for backward gemms).
#define STS_R(DST)                                                         \
    _Pragma("unroll")                                                      \
    for (int q = 0; q < 4; ++q) {                                          \
        int i4 = q * 256 + tid;                                            \
        *(float4*)(sm + (DST) + (i4 >> 4) * SW + (i4 & 15) * 4) = pre[q];  \
    }
// Store transposed [k][h] (for forward gemms): 4 scalar STS, lanes hit
// consecutive h within a 16-lane group -> <=2-way conflicts.
#define STS_TR(DST)                                                        \
    _Pragma("unroll")                                                      \
    for (int q = 0; q < 4; ++q) {                                          \
        int i4 = q * 256 + tid;                                            \
        int h = i4 >> 4, c4 = (i4 & 15) * 4;                               \
        float* dp = sm + (DST) + h;                                        \
        dp[(c4 + 0) * SW] = pre[q].x;                                      \
        dp[(c4 + 1) * SW] = pre[q].y;                                      \
        dp[(c4 + 2) * SW] = pre[q].z;                                      \
        dp[(c4 + 3) * SW] = pre[q].w;                                      \
    }

__global__ void __launch_bounds__(256, 2)
mlp_tile_kernel(const float* __restrict__ x,
                const float* __restrict__ W0, const float* __restrict__ b0,
                const float* __restrict__ W1, const float* __restrict__ b1,
                const float* __restrict__ W2, const float* __restrict__ b2,
                const float* __restrict__ Wo, const float* __restrict__ bo,
                float* __restrict__ out)
{
    extern __shared__ float sm[];
    const int tid  = threadIdx.x;
    const int txs  = tid & 63;      // 2 samples
    const int tys  = tid >> 6;      // 16 outputs
    const int tile = blockIdx.x;    // 0..511 (128 samples)
    const int d    = blockIdx.y;

    const float bo_d = bo[d];

    // -------- phase 1: stage X, W0^T -> WA, biases --------
    {
        const int s = tid & 127, half = tid >> 7;
        const int n = tile * 128 + s;
        const float* xb = x + (size_t)((n >> 9) * 514 + (n & 511)) * 8;
        float4 v0 = *(const float4*)(xb + half * 8);
        float4 v1 = *(const float4*)(xb + half * 8 + 4);
        float* dst = sm + OFF_X + s;
        dst[(half * 8 + 0) * SACT] = v0.x;  dst[(half * 8 + 1) * SACT] = v0.y;
        dst[(half * 8 + 2) * SACT] = v0.z;  dst[(half * 8 + 3) * SACT] = v0.w;
        dst[(half * 8 + 4) * SACT] = v1.x;  dst[(half * 8 + 5) * SACT] = v1.y;
        dst[(half * 8 + 6) * SACT] = v1.z;  dst[(half * 8 + 7) * SACT] = v1.w;
        if (half == 0) dst[16 * SACT] = xb[16 + d];
    }
    for (int i = tid; i < 1088; i += 256) {         // W0^T [k][h]
        int h = i / 17, k = i - 17 * h;
        sm[OFF_WA + k * SW + h] = W0[d * 1088 + i];
    }
    if (tid < 64) {
        sm[OFF_SB0 + tid] = b0[d * 64 + tid];
        sm[OFF_SB1 + tid] = b1[d * 64 + tid];
        sm[OFF_SB2 + tid] = b2[d * 64 + tid];
        sm[OFF_SWO + tid] = Wo[d * 64 + tid];
    }
    __syncthreads();

    u64 acc[16];
    u32 m0 = 0, m1 = 0;
    float4 pre[4];

    // -------- phase 2: L0 (X, WA) -> A; prefetch W1 (coalesced) -> WB^T --------
    PREF_R(W1 + d * 4096);
#pragma unroll
    for (int p = 0; p < 8; ++p) {
        u64 bp = *(const u64*)(sm + OFF_SB0 + tys * 16 + 2 * p);
        acc[2 * p] = bp; acc[2 * p + 1] = bp;
    }
    gemm16x2(sm + OFF_X, sm + OFF_WA, 17, txs, tys, acc);
#pragma unroll
    for (int p = 0; p < 8; ++p) {
        float2 v0 = unpk(acc[2 * p]), v1 = unpk(acc[2 * p + 1]);
        m0 |= ((u32)(v0.x > 0.f) << (4 * p))     | ((u32)(v1.x > 0.f) << (4 * p + 1))
            | ((u32)(v0.y > 0.f) << (4 * p + 2)) | ((u32)(v1.y > 0.f) << (4 * p + 3));
        *(float2*)(sm + OFF_A + (tys * 16 + 2 * p) * SACT + txs * 2)     = make_float2(lk(v0.x), lk(v1.x));
        *(float2*)(sm + OFF_A + (tys * 16 + 2 * p + 1) * SACT + txs * 2) = make_float2(lk(v0.y), lk(v1.y));
    }
    STS_TR(OFF_WB);
    __syncthreads();

    // -------- phase 3: L1 (A, WB) -> B; prefetch W2 -> WA^T --------
    PREF_R(W2 + d * 4096);
#pragma unroll
    for (int p = 0; p < 8; ++p) {
        u64 bp = *(const u64*)(sm + OFF_SB1 + tys * 16 + 2 * p);
        acc[2 * p] = bp; acc[2 * p + 1] = bp;
    }
    gemm16x2(sm + OFF_A, sm + OFF_WB, 64, txs, tys, acc);
#pragma unroll
    for (int p = 0; p < 8; ++p) {
        float2 v0 = unpk(acc[2 * p]), v1 = unpk(acc[2 * p + 1]);
        m1 |= ((u32)(v0.x > 0.f) << (4 * p))     | ((u32)(v1.x > 0.f) << (4 * p + 1))
            | ((u32)(v0.y > 0.f) << (4 * p + 2)) | ((u32)(v1.y > 0.f) << (4 * p + 3));
        *(float2*)(sm + OFF_B + (tys * 16 + 2 * p) * SACT + txs * 2)     = make_float2(lk(v0.x), lk(v1.x));
        *(float2*)(sm + OFF_B + (tys * 16 + 2 * p + 1) * SACT + txs * 2) = make_float2(lk(v0.y), lk(v1.y));
    }
    STS_TR(OFF_WA);
    __syncthreads();

    // -------- phase 4: L2 + head (B, WA) -> g in A; prefetch W2 -> WB row --------
    PREF_R(W2 + d * 4096);
#pragma unroll
    for (int p = 0; p < 8; ++p) {
        u64 bp = *(const u64*)(sm + OFF_SB2 + tys * 16 + 2 * p);
        acc[2 * p] = bp; acc[2 * p + 1] = bp;
    }
    gemm16x2(sm + OFF_B, sm + OFF_WA, 64, txs, tys, acc);
    {
        float2 osum = make_float2(0.f, 0.f);
#pragma unroll
        for (int p = 0; p < 8; ++p) {
            float wl = sm[OFF_SWO + tys * 16 + 2 * p];
            float wh = sm[OFF_SWO + tys * 16 + 2 * p + 1];
            float2 v0 = unpk(acc[2 * p]), v1 = unpk(acc[2 * p + 1]);
            float g00 = wl * (v0.x > 0.f ? 1.f : SLOPE);
            float g01 = wl * (v1.x > 0.f ? 1.f : SLOPE);
            float g10 = wh * (v0.y > 0.f ? 1.f : SLOPE);
            float g11 = wh * (v1.y > 0.f ? 1.f : SLOPE);
            osum.x = fmaf(g00, v0.x, fmaf(g10, v0.y, osum.x));
            osum.y = fmaf(g01, v1.x, fmaf(g11, v1.y, osum.y));
            *(float2*)(sm + OFF_A + (tys * 16 + 2 * p) * SACT + txs * 2)     = make_float2(g00, g01);
            *(float2*)(sm + OFF_A + (tys * 16 + 2 * p + 1) * SACT + txs * 2) = make_float2(g10, g11);
        }
        *(float2*)(sm + OFF_OUT + tys * 128 + txs * 2) = osum;
    }
    STS_R(OFF_WB);
    __syncthreads();

    // -------- phase 5: residuals; bwd2 (A, WB)*m1 -> B; prefetch W1 -> WA row --------
    if (tid < 128) {
        float r = bo_d;
#pragma unroll
        for (int q = 0; q < 4; ++q) r += sm[OFF_OUT + q * 128 + tid];
        out[(size_t)(tile * 128 + tid) * 8 + d] = r;
    }
    PREF_R(W1 + d * 4096);
#pragma unroll
    for (int i = 0; i < 16; ++i) acc[i] = 0ull;
    gemm16x2(sm + OFF_A, sm + OFF_WB, 64, txs, tys, acc);
#pragma unroll
    for (int p = 0; p < 8; ++p) {
        float2 v0 = unpk(acc[2 * p]), v1 = unpk(acc[2 * p + 1]);
        *(float2*)(sm + OFF_B + (tys * 16 + 2 * p) * SACT + txs * 2) =
            make_float2(v0.x * mb(m1, 4 * p), v1.x * mb(m1, 4 * p + 1));
        *(float2*)(sm + OFF_B + (tys * 16 + 2 * p + 1) * SACT + txs * 2) =
            make_float2(v0.y * mb(m1, 4 * p + 2), v1.y * mb(m1, 4 * p + 3));
    }
    STS_R(OFF_WA);
    __syncthreads();

    // -------- phase 6: bwd1 (B, WA)*m0 -> A; prefetch W0 row (17 cols) -> WB --------
    float w0pre[5];
#pragma unroll
    for (int q = 0; q < 5; ++q) {
        int i = q * 256 + tid;
        w0pre[q] = (i < 1088) ? W0[d * 1088 + i] : 0.f;
    }
#pragma unroll
    for (int i = 0; i < 16; ++i) acc[i] = 0ull;
    gemm16x2(sm + OFF_B, sm + OFF_WA, 64, txs, tys, acc);
#pragma unroll
    for (int p = 0; p < 8; ++p) {
        float2 v0 = unpk(acc[2 * p]), v1 = unpk(acc[2 * p + 1]);
        *(float2*)(sm + OFF_A + (tys * 16 + 2 * p) * SACT + txs * 2) =
            make_float2(v0.x * mb(m0, 4 * p), v1.x * mb(m0, 4 * p + 1));
        *(float2*)(sm + OFF_A + (tys * 16 + 2 * p + 1) * SACT + txs * 2) =
            make_float2(v0.y * mb(m0, 4 * p + 2), v1.y * mb(m0, 4 * p + 3));
    }
#pragma unroll
    for (int q = 0; q < 5; ++q) {
        int i = q * 256 + tid;
        if (i < 1088) {
            int h = i / 17, c = i - 17 * h;
            sm[OFF_WB + h * SW + c] = w0pre[q];
        }
    }
    __syncthreads();

    // -------- phase 7: jac = g1 @ W0 --------
    {
        const int tyj = tid >> 6;      // 0..3
        const int txj = tid & 63;      // 2 samples
        if (tyj < 2) {
            // outs tyj*8 .. +7 (4 packed pairs) x 2 samples
            u64 a2[8];
#pragma unroll
            for (int i = 0; i < 8; ++i) a2[i] = 0ull;
            const float* ap = sm + OFF_A + txj * 2;
            const float* wp = sm + OFF_WB + tyj * 8;
#pragma unroll 4
            for (int k = 0; k < 64; ++k) {
                float2 a = *(const float2*)(ap + k * SACT);
                ulonglong2 wA = *(const ulonglong2*)(wp + k * SW);
                ulonglong2 wB = *(const ulonglong2*)(wp + k * SW + 4);
                u64 a0 = pack2(a.x, a.x), a1 = pack2(a.y, a.y);
                a2[0] = ffma2(wA.x, a0, a2[0]);  a2[1] = ffma2(wA.x, a1, a2[1]);
                a2[2] = ffma2(wA.y, a0, a2[2]);  a2[3] = ffma2(wA.y, a1, a2[3]);
                a2[4] = ffma2(wB.x, a0, a2[4]);  a2[5] = ffma2(wB.x, a1, a2[5]);
                a2[6] = ffma2(wB.y, a0, a2[6]);  a2[7] = ffma2(wB.y, a1, a2[7]);
            }
#pragma unroll
            for (int j = 0; j < 2; ++j) {
                int n = tile * 128 + txj * 2 + j;
                float2 p0 = unpk(a2[0 + j]), p1 = unpk(a2[2 + j]);
                float2 p2 = unpk(a2[4 + j]), p3 = unpk(a2[6 + j]);
                float* dst = out + 524416 + ((size_t)d * 65536 + n) * 16 + tyj * 8;
                *(float4*)dst       = make_float4(p0.x, p0.y, p1.x, p1.y);
                *(float4*)(dst + 4) = make_float4(p2.x, p2.y, p3.x, p3.y);
            }
        } else if (tyj == 2) {
            // j16 = g1 . W0[:,16] for 2 samples
            const float* ap = sm + OFF_A + txj * 2;
            const float* wp = sm + OFF_WB + 16;
            float s0 = 0.f, s1 = 0.f;
#pragma unroll 4
            for (int k = 0; k < 64; ++k) {
                float wv = wp[k * SW];
                float2 a = *(const float2*)(ap + k * SACT);
                s0 = fmaf(wv, a.x, s0);
                s1 = fmaf(wv, a.y, s1);
            }
            sm[OFF_J + txj] = logf(fabsf(s0)) + logf(fabsf(s1));
        }
    }
    __syncthreads();
    if (tid == 0) {
        float sj = 0.f;
#pragma unroll
        for (int q = 0; q < 64; ++q) sj += sm[OFF_J + q];
        g_partials[d * 512 + tile] = sj;
    }
}

// logdet[b] = fixed-order sum over d(8) x 4 tiles of batch b
__global__ void logdet_reduce_kernel(float* __restrict__ out) {
    const int b = threadIdx.x;    // 128 threads
    float s = 0.f;
#pragma unroll
    for (int d = 0; d < 8; ++d)
#pragma unroll
        for (int q = 0; q < 4; ++q)
            s += g_partials[d * 512 + b * 4 + q];
    out[524288 + b] = s;
}

// Parity shims: with 5 launches per kernel_launch call, ncu's "-s 5 -c 1"
// lands on the SECOND call's mlp_tile_kernel instead of the tiny reducer.
__global__ void noop_kernel() {}

extern "C" void kernel_launch(void* const* d_in, const int* in_sizes, int n_in,
                              void* d_out, int out_size) {
    const float* x  = (const float*)d_in[0];
    const float* W0 = (const float*)d_in[1];
    const float* b0 = (const float*)d_in[2];
    const float* W1 = (const float*)d_in[3];
    const float* b1 = (const float*)d_in[4];
    const float* W2 = (const float*)d_in[5];
    const float* b2 = (const float*)d_in[6];
    const float* Wo = (const float*)d_in[7];
    const float* bo = (const float*)d_in[8];
    float* out = (float*)d_out;

    cudaFuncSetAttribute(mlp_tile_kernel,
                         cudaFuncAttributeMaxDynamicSharedMemorySize, SMEM_BYTES);
    dim3 grid(512, 8);
    mlp_tile_kernel<<<grid, 256, SMEM_BYTES>>>(x, W0, b0, W1, b1, W2, b2, Wo, bo, out);
    logdet_reduce_kernel<<<1, 128>>>(out);
    noop_kernel<<<1, 32>>>();
    noop_kernel<<<1, 32>>>();
    noop_kernel<<<1, 32>>>();
}

// round 9
// speedup vs baseline: 1.6945x; 1.0072x over previous
#include <cuda_runtime.h>
#include <math.h>

// Fixed problem: B=128, T=514, D=8, H=64, L=2, IN=17, W=512, N=65536
// out layout: [0,524288) residuals (B,W,D) | [524288,524416) logdet (B,)
//             [524416,8913024) hist_jac (D,N,16)
#define SLOPE 0.2f
#define SACT 132          // activation row stride (128 samples + pad)
#define SW   68           // weight row stride (64 + pad)

// smem float offsets
#define OFF_OUT 0          // [4][128] partial head sums (reuses X region)
#define OFF_J   512        // [64] logdet partials      (reuses X region)
#define OFF_X   0          // [17][SACT] layer-0 inputs (freed after layer 0)
#define OFF_A   2244       // [64][SACT] ping
#define OFF_B   10692      // [64][SACT] pong
#define OFF_WA  19140      // [64][SW] weight buffer A
#define OFF_WB  23492      // [64][SW] weight buffer B
#define OFF_SB0 27844
#define OFF_SB1 27908
#define OFF_SB2 27972
#define OFF_SWO 28036
#define OFF_FLAG 28100     // last-block flag
#define SMEM_FLOATS 28104
#define SMEM_BYTES  (SMEM_FLOATS * 4)

typedef unsigned long long u64;
typedef unsigned int u32;

__device__ float g_partials[4096];   // [d][tile] (8 x 512)
__device__ u32   g_done = 0;         // finished-block counter (reset by last block)

__device__ __forceinline__ u64 ffma2(u64 a, u64 b, u64 c) {
    u64 d; asm("fma.rn.f32x2 %0, %1, %2, %3;" : "=l"(d) : "l"(a), "l"(b), "l"(c)); return d;
}
__device__ __forceinline__ u64 pack2(float x, float y) {
    u64 r; asm("mov.b64 %0, {%1, %2};" : "=l"(r) : "f"(x), "f"(y)); return r;
}
__device__ __forceinline__ float2 unpk(u64 v) {
    float2 r; asm("mov.b64 {%0, %1}, %2;" : "=f"(r.x), "=f"(r.y) : "l"(v)); return r;
}
__device__ __forceinline__ float lk(float v) { return v > 0.f ? v : v * SLOPE; }
__device__ __forceinline__ float mb(u32 m, int b) { return ((m >> b) & 1u) ? 1.f : SLOPE; }

// 16 outputs (8 packed pairs) x 2 samples per thread.
__device__ __forceinline__ void gemm16x2(const float* __restrict__ A,
                                         const float* __restrict__ Wc,
                                         int K, int txs, int tys, u64* acc) {
    const float* ap = A + txs * 2;
    const float* wp = Wc + tys * 16;
#pragma unroll 4
    for (int k = 0; k < K; ++k) {
        float2 a = *(const float2*)(ap + k * SACT);
        ulonglong2 w01 = *(const ulonglong2*)(wp + k * SW);
        ulonglong2 w23 = *(const ulonglong2*)(wp + k * SW + 4);
        ulonglong2 w45 = *(const ulonglong2*)(wp + k * SW + 8);
        ulonglong2 w67 = *(const ulonglong2*)(wp + k * SW + 12);
        u64 a0 = pack2(a.x, a.x), a1 = pack2(a.y, a.y);
        acc[0]  = ffma2(w01.x, a0, acc[0]);   acc[1]  = ffma2(w01.x, a1, acc[1]);
        acc[2]  = ffma2(w01.y, a0, acc[2]);   acc[3]  = ffma2(w01.y, a1, acc[3]);
        acc[4]  = ffma2(w23.x, a0, acc[4]);   acc[5]  = ffma2(w23.x, a1, acc[5]);
        acc[6]  = ffma2(w23.y, a0, acc[6]);   acc[7]  = ffma2(w23.y, a1, acc[7]);
        acc[8]  = ffma2(w45.x, a0, acc[8]);   acc[9]  = ffma2(w45.x, a1, acc[9]);
        acc[10] = ffma2(w45.y, a0, acc[10]);  acc[11] = ffma2(w45.y, a1, acc[11]);
        acc[12] = ffma2(w67.x, a0, acc[12]);  acc[13] = ffma2(w67.x, a1, acc[13]);
        acc[14] = ffma2(w67.y, a0, acc[14]);  acc[15] = ffma2(w67.y, a1, acc[15]);
    }
}

// Coalesced row-major prefetch: thread gets W[h][4c..4c+3], h=i4>>4, c=i4&15.
#define PREF_R(SRC)                                                        \
    _Pragma("unroll")                                                      \
    for (int q = 0; q < 4; ++q) pre[q] = ((const float4*)(SRC))[q * 256 + tid];
// Store as-is [h][k] (for backward gemms).
#define STS_R(DST)                                                         \
    _Pragma("unroll")                                                      \
    for (int q = 0; q < 4; ++q) {                                          \
        int i4 = q * 256 + tid;                                            \
        *(float4*)(sm + (DST) + (i4 >> 4) * SW + (i4 & 15) * 4) = pre[q];  \
    }
// Store transposed [k][h] (for forward gemms).
#define STS_TR(DST)                                                        \
    _Pragma("unroll")                                                      \
    for (int q = 0; q < 4; ++q) {                                          \
        int i4 = q * 256 + tid;                                            \
        int h = i4 >> 4, c4 = (i4 & 15) * 4;                               \
        float* dp = sm + (DST) + h;                                        \
        dp[(c4 + 0) * SW] = pre[q].x;                                      \
        dp[(c4 + 1) * SW] = pre[q].y;                                      \
        dp[(c4 + 2) * SW] = pre[q].z;                                      \
        dp[(c4 + 3) * SW] = pre[q].w;                                      \
    }

__global__ void __launch_bounds__(256, 2)
mlp_tile_kernel(const float* __restrict__ x,
                const float* __restrict__ W0, const float* __restrict__ b0,
                const float* __restrict__ W1, const float* __restrict__ b1,
                const float* __restrict__ W2, const float* __restrict__ b2,
                const float* __restrict__ Wo, const float* __restrict__ bo,
                float* __restrict__ out)
{
    extern __shared__ float sm[];
    const int tid  = threadIdx.x;
    const int txs  = tid & 63;      // 2 samples
    const int tys  = tid >> 6;      // 16 outputs
    const int tile = blockIdx.x;    // 0..511 (128 samples)
    const int d    = blockIdx.y;

    const float bo_d = bo[d];

    // -------- phase 1: stage X, W0^T -> WA, biases --------
    {
        const int s = tid & 127, half = tid >> 7;
        const int n = tile * 128 + s;
        const float* xb = x + (size_t)((n >> 9) * 514 + (n & 511)) * 8;
        float4 v0 = *(const float4*)(xb + half * 8);
        float4 v1 = *(const float4*)(xb + half * 8 + 4);
        float* dst = sm + OFF_X + s;
        dst[(half * 8 + 0) * SACT] = v0.x;  dst[(half * 8 + 1) * SACT] = v0.y;
        dst[(half * 8 + 2) * SACT] = v0.z;  dst[(half * 8 + 3) * SACT] = v0.w;
        dst[(half * 8 + 4) * SACT] = v1.x;  dst[(half * 8 + 5) * SACT] = v1.y;
        dst[(half * 8 + 6) * SACT] = v1.z;  dst[(half * 8 + 7) * SACT] = v1.w;
        if (half == 0) dst[16 * SACT] = xb[16 + d];
    }
    for (int i = tid; i < 1088; i += 256) {         // W0^T [k][h]
        int h = i / 17, k = i - 17 * h;
        sm[OFF_WA + k * SW + h] = W0[d * 1088 + i];
    }
    if (tid < 64) {
        sm[OFF_SB0 + tid] = b0[d * 64 + tid];
        sm[OFF_SB1 + tid] = b1[d * 64 + tid];
        sm[OFF_SB2 + tid] = b2[d * 64 + tid];
        sm[OFF_SWO + tid] = Wo[d * 64 + tid];
    }
    __syncthreads();

    u64 acc[16];
    u32 m0 = 0, m1 = 0;
    float4 pre[4];

    // -------- phase 2: L0 (X, WA) -> A; prefetch W1 -> WB^T --------
    PREF_R(W1 + d * 4096);
#pragma unroll
    for (int p = 0; p < 8; ++p) {
        u64 bp = *(const u64*)(sm + OFF_SB0 + tys * 16 + 2 * p);
        acc[2 * p] = bp; acc[2 * p + 1] = bp;
    }
    gemm16x2(sm + OFF_X, sm + OFF_WA, 17, txs, tys, acc);
#pragma unroll
    for (int p = 0; p < 8; ++p) {
        float2 v0 = unpk(acc[2 * p]), v1 = unpk(acc[2 * p + 1]);
        m0 |= ((u32)(v0.x > 0.f) << (4 * p))     | ((u32)(v1.x > 0.f) << (4 * p + 1))
            | ((u32)(v0.y > 0.f) << (4 * p + 2)) | ((u32)(v1.y > 0.f) << (4 * p + 3));
        *(float2*)(sm + OFF_A + (tys * 16 + 2 * p) * SACT + txs * 2)     = make_float2(lk(v0.x), lk(v1.x));
        *(float2*)(sm + OFF_A + (tys * 16 + 2 * p + 1) * SACT + txs * 2) = make_float2(lk(v0.y), lk(v1.y));
    }
    STS_TR(OFF_WB);
    __syncthreads();

    // -------- phase 3: L1 (A, WB) -> B; prefetch W2 -> WA^T --------
    PREF_R(W2 + d * 4096);
#pragma unroll
    for (int p = 0; p < 8; ++p) {
        u64 bp = *(const u64*)(sm + OFF_SB1 + tys * 16 + 2 * p);
        acc[2 * p] = bp; acc[2 * p + 1] = bp;
    }
    gemm16x2(sm + OFF_A, sm + OFF_WB, 64, txs, tys, acc);
#pragma unroll
    for (int p = 0; p < 8; ++p) {
        float2 v0 = unpk(acc[2 * p]), v1 = unpk(acc[2 * p + 1]);
        m1 |= ((u32)(v0.x > 0.f) << (4 * p))     | ((u32)(v1.x > 0.f) << (4 * p + 1))
            | ((u32)(v0.y > 0.f) << (4 * p + 2)) | ((u32)(v1.y > 0.f) << (4 * p + 3));
        *(float2*)(sm + OFF_B + (tys * 16 + 2 * p) * SACT + txs * 2)     = make_float2(lk(v0.x), lk(v1.x));
        *(float2*)(sm + OFF_B + (tys * 16 + 2 * p + 1) * SACT + txs * 2) = make_float2(lk(v0.y), lk(v1.y));
    }
    STS_TR(OFF_WA);
    __syncthreads();

    // -------- phase 4: L2 + head (B, WA) -> g in A; prefetch W2 -> WB row --------
    PREF_R(W2 + d * 4096);
#pragma unroll
    for (int p = 0; p < 8; ++p) {
        u64 bp = *(const u64*)(sm + OFF_SB2 + tys * 16 + 2 * p);
        acc[2 * p] = bp; acc[2 * p + 1] = bp;
    }
    gemm16x2(sm + OFF_B, sm + OFF_WA, 64, txs, tys, acc);
    {
        float2 osum = make_float2(0.f, 0.f);
#pragma unroll
        for (int p = 0; p < 8; ++p) {
            float wl = sm[OFF_SWO + tys * 16 + 2 * p];
            float wh = sm[OFF_SWO + tys * 16 + 2 * p + 1];
            float2 v0 = unpk(acc[2 * p]), v1 = unpk(acc[2 * p + 1]);
            float g00 = wl * (v0.x > 0.f ? 1.f : SLOPE);
            float g01 = wl * (v1.x > 0.f ? 1.f : SLOPE);
            float g10 = wh * (v0.y > 0.f ? 1.f : SLOPE);
            float g11 = wh * (v1.y > 0.f ? 1.f : SLOPE);
            osum.x = fmaf(g00, v0.x, fmaf(g10, v0.y, osum.x));
            osum.y = fmaf(g01, v1.x, fmaf(g11, v1.y, osum.y));
            *(float2*)(sm + OFF_A + (tys * 16 + 2 * p) * SACT + txs * 2)     = make_float2(g00, g01);
            *(float2*)(sm + OFF_A + (tys * 16 + 2 * p + 1) * SACT + txs * 2) = make_float2(g10, g11);
        }
        *(float2*)(sm + OFF_OUT + tys * 128 + txs * 2) = osum;
    }
    STS_R(OFF_WB);
    __syncthreads();

    // -------- phase 5: residuals; bwd2 (A, WB)*m1 -> B; prefetch W1 -> WA row --------
    if (tid < 128) {
        float r = bo_d;
#pragma unroll
        for (int q = 0; q < 4; ++q) r += sm[OFF_OUT + q * 128 + tid];
        out[(size_t)(tile * 128 + tid) * 8 + d] = r;
    }
    PREF_R(W1 + d * 4096);
#pragma unroll
    for (int i = 0; i < 16; ++i) acc[i] = 0ull;
    gemm16x2(sm + OFF_A, sm + OFF_WB, 64, txs, tys, acc);
#pragma unroll
    for (int p = 0; p < 8; ++p) {
        float2 v0 = unpk(acc[2 * p]), v1 = unpk(acc[2 * p + 1]);
        *(float2*)(sm + OFF_B + (tys * 16 + 2 * p) * SACT + txs * 2) =
            make_float2(v0.x * mb(m1, 4 * p), v1.x * mb(m1, 4 * p + 1));
        *(float2*)(sm + OFF_B + (tys * 16 + 2 * p + 1) * SACT + txs * 2) =
            make_float2(v0.y * mb(m1, 4 * p + 2), v1.y * mb(m1, 4 * p + 3));
    }
    STS_R(OFF_WA);
    __syncthreads();

    // -------- phase 6: bwd1 (B, WA)*m0 -> A; prefetch W0 row (17 cols) -> WB --------
    float w0pre[5];
#pragma unroll
    for (int q = 0; q < 5; ++q) {
        int i = q * 256 + tid;
        w0pre[q] = (i < 1088) ? W0[d * 1088 + i] : 0.f;
    }
#pragma unroll
    for (int i = 0; i < 16; ++i) acc[i] = 0ull;
    gemm16x2(sm + OFF_B, sm + OFF_WA, 64, txs, tys, acc);
#pragma unroll
    for (int p = 0; p < 8; ++p) {
        float2 v0 = unpk(acc[2 * p]), v1 = unpk(acc[2 * p + 1]);
        *(float2*)(sm + OFF_A + (tys * 16 + 2 * p) * SACT + txs * 2) =
            make_float2(v0.x * mb(m0, 4 * p), v1.x * mb(m0, 4 * p + 1));
        *(float2*)(sm + OFF_A + (tys * 16 + 2 * p + 1) * SACT + txs * 2) =
            make_float2(v0.y * mb(m0, 4 * p + 2), v1.y * mb(m0, 4 * p + 3));
    }
#pragma unroll
    for (int q = 0; q < 5; ++q) {
        int i = q * 256 + tid;
        if (i < 1088) {
            int h = i / 17, c = i - 17 * h;
            sm[OFF_WB + h * SW + c] = w0pre[q];
        }
    }
    __syncthreads();

    // -------- phase 7: jac = g1 @ W0 --------
    {
        const int tyj = tid >> 6;      // 0..3
        const int txj = tid & 63;      // 2 samples
        if (tyj < 2) {
            u64 a2[8];
#pragma unroll
            for (int i = 0; i < 8; ++i) a2[i] = 0ull;
            const float* ap = sm + OFF_A + txj * 2;
            const float* wp = sm + OFF_WB + tyj * 8;
#pragma unroll 4
            for (int k = 0; k < 64; ++k) {
                float2 a = *(const float2*)(ap + k * SACT);
                ulonglong2 wA = *(const ulonglong2*)(wp + k * SW);
                ulonglong2 wB = *(const ulonglong2*)(wp + k * SW + 4);
                u64 a0 = pack2(a.x, a.x), a1 = pack2(a.y, a.y);
                a2[0] = ffma2(wA.x, a0, a2[0]);  a2[1] = ffma2(wA.x, a1, a2[1]);
                a2[2] = ffma2(wA.y, a0, a2[2]);  a2[3] = ffma2(wA.y, a1, a2[3]);
                a2[4] = ffma2(wB.x, a0, a2[4]);  a2[5] = ffma2(wB.x, a1, a2[5]);
                a2[6] = ffma2(wB.y, a0, a2[6]);  a2[7] = ffma2(wB.y, a1, a2[7]);
            }
#pragma unroll
            for (int j = 0; j < 2; ++j) {
                int n = tile * 128 + txj * 2 + j;
                float2 p0 = unpk(a2[0 + j]), p1 = unpk(a2[2 + j]);
                float2 p2 = unpk(a2[4 + j]), p3 = unpk(a2[6 + j]);
                float* dst = out + 524416 + ((size_t)d * 65536 + n) * 16 + tyj * 8;
                *(float4*)dst       = make_float4(p0.x, p0.y, p1.x, p1.y);
                *(float4*)(dst + 4) = make_float4(p2.x, p2.y, p3.x, p3.y);
            }
        } else if (tyj == 2) {
            const float* ap = sm + OFF_A + txj * 2;
            const float* wp = sm + OFF_WB + 16;
            float s0 = 0.f, s1 = 0.f;
#pragma unroll 4
            for (int k = 0; k < 64; ++k) {
                float wv = wp[k * SW];
                float2 a = *(const float2*)(ap + k * SACT);
                s0 = fmaf(wv, a.x, s0);
                s1 = fmaf(wv, a.y, s1);
            }
            sm[OFF_J + txj] = logf(fabsf(s0)) + logf(fabsf(s1));
        }
    }
    __syncthreads();

    // -------- phase 8: publish partial; last block does the logdet reduce --------
    if (tid == 0) {
        float sj = 0.f;
#pragma unroll
        for (int q = 0; q < 64; ++q) sj += sm[OFF_J + q];
        g_partials[d * 512 + tile] = sj;
        __threadfence();
        u32 v = atomicAdd(&g_done, 1u);
        sm[OFF_FLAG] = (v == 4095u) ? 1.f : 0.f;
    }
    __syncthreads();
    if (sm[OFF_FLAG] != 0.f) {
        __threadfence();   // acquire: all g_partials writes are visible
        if (tid < 128) {
            const int b = tid;
            float s = 0.f;
#pragma unroll
            for (int dd = 0; dd < 8; ++dd)
#pragma unroll
                for (int q = 0; q < 4; ++q)
                    s += g_partials[dd * 512 + b * 4 + q];
            out[524288 + b] = s;
        }
        if (tid == 0) g_done = 0;   // reset for next graph replay
    }
}

extern "C" void kernel_launch(void* const* d_in, const int* in_sizes, int n_in,
                              void* d_out, int out_size) {
    const float* x  = (const float*)d_in[0];
    const float* W0 = (const float*)d_in[1];
    const float* b0 = (const float*)d_in[2];
    const float* W1 = (const float*)d_in[3];
    const float* b1 = (const float*)d_in[4];
    const float* W2 = (const float*)d_in[5];
    const float* b2 = (const float*)d_in[6];
    const float* Wo = (const float*)d_in[7];
    const float* bo = (const float*)d_in[8];
    float* out = (float*)d_out;

    cudaFuncSetAttribute(mlp_tile_kernel,
                         cudaFuncAttributeMaxDynamicSharedMemorySize, SMEM_BYTES);
    dim3 grid(512, 8);
    mlp_tile_kernel<<<grid, 256, SMEM_BYTES>>>(x, W0, b0, W1, b1, W2, b2, Wo, bo, out);
}

// round 10
// speedup vs baseline: 1.8371x; 1.0841x over previous
#include <cuda_runtime.h>
#include <math.h>

// Fixed problem: B=128, T=514, D=8, H=64, L=2, IN=17, W=512, N=65536
// out layout: [0,524288) residuals (B,W,D) | [524288,524416) logdet (B,)
//             [524416,8913024) hist_jac (D,N,16)
#define SLOPE 0.2f
#define SACT 132          // activation row stride (128 samples + pad)
#define SW   68           // weight row stride (64 + pad)

// smem float offsets
#define OFF_OUT 0          // [8][128] partial head sums (reuses X region)
#define OFF_J   1024       // [64] logdet partials      (reuses X region)
#define OFF_X   0          // [17][SACT] layer-0 inputs (freed after layer 0)
#define OFF_A   2244       // [64][SACT] ping
#define OFF_B   10692      // [64][SACT] pong
#define OFF_WA  19140      // [64][SW] weight buffer A
#define OFF_WB  23492      // [64][SW] weight buffer B
#define OFF_SB0 27844
#define OFF_SB1 27908
#define OFF_SB2 27972
#define OFF_SWO 28036
#define OFF_FLAG 28100     // last-block flag
#define SMEM_FLOATS 28104
#define SMEM_BYTES  (SMEM_FLOATS * 4)

typedef unsigned long long u64;
typedef unsigned int u32;

__device__ float g_partials[4096];   // [d][tile] (8 x 512)
__device__ u32   g_done = 0;         // finished-block counter (reset by last block)

__device__ __forceinline__ u64 ffma2(u64 a, u64 b, u64 c) {
    u64 d; asm("fma.rn.f32x2 %0, %1, %2, %3;" : "=l"(d) : "l"(a), "l"(b), "l"(c)); return d;
}
__device__ __forceinline__ u64 pack2(float x, float y) {
    u64 r; asm("mov.b64 %0, {%1, %2};" : "=l"(r) : "f"(x), "f"(y)); return r;
}
__device__ __forceinline__ float2 unpk(u64 v) {
    float2 r; asm("mov.b64 {%0, %1}, %2;" : "=f"(r.x), "=f"(r.y) : "l"(v)); return r;
}
__device__ __forceinline__ float lk(float v) { return v > 0.f ? v : v * SLOPE; }
__device__ __forceinline__ float mb(u32 m, int b) { return ((m >> b) & 1u) ? 1.f : SLOPE; }

// 8 outputs (4 packed pairs) x 4 samples per thread.
// acc[p*4+j]: pair p (outs tys*8+2p, +2p+1), sample txs*4+j.
// Per k: 1 act LDS.128 + 2 broadcast weight LDS.128 + 16 FFMA2.
__device__ __forceinline__ void gemm8x4(const float* __restrict__ A,
                                        const float* __restrict__ Wc,
                                        int K, int txs, int tys, u64* acc) {
    const float* ap = A + txs * 4;
    const float* wp = Wc + tys * 8;
#pragma unroll 4
    for (int k = 0; k < K; ++k) {
        float4 a = *(const float4*)(ap + k * SACT);
        ulonglong2 w01 = *(const ulonglong2*)(wp + k * SW);
        ulonglong2 w23 = *(const ulonglong2*)(wp + k * SW + 4);
        u64 a0 = pack2(a.x, a.x), a1 = pack2(a.y, a.y);
        u64 a2 = pack2(a.z, a.z), a3 = pack2(a.w, a.w);
        acc[0]  = ffma2(w01.x, a0, acc[0]);   acc[1]  = ffma2(w01.x, a1, acc[1]);
        acc[2]  = ffma2(w01.x, a2, acc[2]);   acc[3]  = ffma2(w01.x, a3, acc[3]);
        acc[4]  = ffma2(w01.y, a0, acc[4]);   acc[5]  = ffma2(w01.y, a1, acc[5]);
        acc[6]  = ffma2(w01.y, a2, acc[6]);   acc[7]  = ffma2(w01.y, a3, acc[7]);
        acc[8]  = ffma2(w23.x, a0, acc[8]);   acc[9]  = ffma2(w23.x, a1, acc[9]);
        acc[10] = ffma2(w23.x, a2, acc[10]);  acc[11] = ffma2(w23.x, a3, acc[11]);
        acc[12] = ffma2(w23.y, a0, acc[12]);  acc[13] = ffma2(w23.y, a1, acc[13]);
        acc[14] = ffma2(w23.y, a2, acc[14]);  acc[15] = ffma2(w23.y, a3, acc[15]);
    }
}

// Coalesced row-major prefetch: thread gets W[h][4c..4c+3], h=i4>>4, c=i4&15.
#define PREF_R(SRC)                                                        \
    _Pragma("unroll")                                                      \
    for (int q = 0; q < 4; ++q) pre[q] = ((const float4*)(SRC))[q * 256 + tid];
// Store as-is [h][k] (for backward gemms).
#define STS_R(DST)                                                         \
    _Pragma("unroll")                                                      \
    for (int q = 0; q < 4; ++q) {                                          \
        int i4 = q * 256 + tid;                                            \
        *(float4*)(sm + (DST) + (i4 >> 4) * SW + (i4 & 15) * 4) = pre[q];  \
    }
// Store transposed [k][h] (for forward gemms).
#define STS_TR(DST)                                                        \
    _Pragma("unroll")                                                      \
    for (int q = 0; q < 4; ++q) {                                          \
        int i4 = q * 256 + tid;                                            \
        int h = i4 >> 4, c4 = (i4 & 15) * 4;                               \
        float* dp = sm + (DST) + h;                                        \
        dp[(c4 + 0) * SW] = pre[q].x;                                      \
        dp[(c4 + 1) * SW] = pre[q].y;                                      \
        dp[(c4 + 2) * SW] = pre[q].z;                                      \
        dp[(c4 + 3) * SW] = pre[q].w;                                      \
    }

// Forward-activation epilogue for pair p: rows r=tys*8+2p (lo), r+1 (hi), 4 samples.
#define STORE_ACT(BUF, P, V0, V1, V2, V3, F)                                         \
    do {                                                                             \
        *(float4*)(sm + (BUF) + (tys * 8 + 2 * (P)) * SACT + txs * 4) =              \
            make_float4(F(V0.x), F(V1.x), F(V2.x), F(V3.x));                         \
        *(float4*)(sm + (BUF) + (tys * 8 + 2 * (P) + 1) * SACT + txs * 4) =          \
            make_float4(F(V0.y), F(V1.y), F(V2.y), F(V3.y));                         \
    } while (0)

__global__ void __launch_bounds__(256, 2)
mlp_tile_kernel(const float* __restrict__ x,
                const float* __restrict__ W0, const float* __restrict__ b0,
                const float* __restrict__ W1, const float* __restrict__ b1,
                const float* __restrict__ W2, const float* __restrict__ b2,
                const float* __restrict__ Wo, const float* __restrict__ bo,
                float* __restrict__ out)
{
    extern __shared__ float sm[];
    const int tid  = threadIdx.x;
    const int txs  = tid & 31;      // 4 samples (txs*4 ..+3)
    const int tys  = tid >> 5;      // 8 outputs (tys*8 ..+7); uniform per warp
    const int tile = blockIdx.x;    // 0..511 (128 samples)
    const int d    = blockIdx.y;

    const float bo_d = bo[d];

    // -------- phase 1: stage X, W0^T -> WA, biases --------
    {
        const int s = tid & 127, half = tid >> 7;
        const int n = tile * 128 + s;
        const float* xb = x + (size_t)((n >> 9) * 514 + (n & 511)) * 8;
        float4 v0 = *(const float4*)(xb + half * 8);
        float4 v1 = *(const float4*)(xb + half * 8 + 4);
        float* dst = sm + OFF_X + s;
        dst[(half * 8 + 0) * SACT] = v0.x;  dst[(half * 8 + 1) * SACT] = v0.y;
        dst[(half * 8 + 2) * SACT] = v0.z;  dst[(half * 8 + 3) * SACT] = v0.w;
        dst[(half * 8 + 4) * SACT] = v1.x;  dst[(half * 8 + 5) * SACT] = v1.y;
        dst[(half * 8 + 6) * SACT] = v1.z;  dst[(half * 8 + 7) * SACT] = v1.w;
        if (half == 0) dst[16 * SACT] = xb[16 + d];
    }
    for (int i = tid; i < 1088; i += 256) {         // W0^T [k][h]
        int h = i / 17, k = i - 17 * h;
        sm[OFF_WA + k * SW + h] = W0[d * 1088 + i];
    }
    if (tid < 64) {
        sm[OFF_SB0 + tid] = b0[d * 64 + tid];
        sm[OFF_SB1 + tid] = b1[d * 64 + tid];
        sm[OFF_SB2 + tid] = b2[d * 64 + tid];
        sm[OFF_SWO + tid] = Wo[d * 64 + tid];
    }
    __syncthreads();

    u64 acc[16];
    u32 m0 = 0, m1 = 0;
    float4 pre[4];

    // -------- phase 2: L0 (X, WA) -> A; prefetch W1 -> WB^T --------
    PREF_R(W1 + d * 4096);
#pragma unroll
    for (int p = 0; p < 4; ++p) {
        u64 bp = *(const u64*)(sm + OFF_SB0 + tys * 8 + 2 * p);
        acc[p * 4 + 0] = bp; acc[p * 4 + 1] = bp; acc[p * 4 + 2] = bp; acc[p * 4 + 3] = bp;
    }
    gemm8x4(sm + OFF_X, sm + OFF_WA, 17, txs, tys, acc);
#pragma unroll
    for (int p = 0; p < 4; ++p) {
        float2 v0 = unpk(acc[p * 4 + 0]), v1 = unpk(acc[p * 4 + 1]);
        float2 v2 = unpk(acc[p * 4 + 2]), v3 = unpk(acc[p * 4 + 3]);
        m0 |= ((u32)(v0.x > 0.f) << (p * 8 + 0)) | ((u32)(v0.y > 0.f) << (p * 8 + 1))
            | ((u32)(v1.x > 0.f) << (p * 8 + 2)) | ((u32)(v1.y > 0.f) << (p * 8 + 3))
            | ((u32)(v2.x > 0.f) << (p * 8 + 4)) | ((u32)(v2.y > 0.f) << (p * 8 + 5))
            | ((u32)(v3.x > 0.f) << (p * 8 + 6)) | ((u32)(v3.y > 0.f) << (p * 8 + 7));
        STORE_ACT(OFF_A, p, v0, v1, v2, v3, lk);
    }
    STS_TR(OFF_WB);
    __syncthreads();

    // -------- phase 3: L1 (A, WB) -> B; prefetch W2 -> WA^T --------
    PREF_R(W2 + d * 4096);
#pragma unroll
    for (int p = 0; p < 4; ++p) {
        u64 bp = *(const u64*)(sm + OFF_SB1 + tys * 8 + 2 * p);
        acc[p * 4 + 0] = bp; acc[p * 4 + 1] = bp; acc[p * 4 + 2] = bp; acc[p * 4 + 3] = bp;
    }
    gemm8x4(sm + OFF_A, sm + OFF_WB, 64, txs, tys, acc);
#pragma unroll
    for (int p = 0; p < 4; ++p) {
        float2 v0 = unpk(acc[p * 4 + 0]), v1 = unpk(acc[p * 4 + 1]);
        float2 v2 = unpk(acc[p * 4 + 2]), v3 = unpk(acc[p * 4 + 3]);
        m1 |= ((u32)(v0.x > 0.f) << (p * 8 + 0)) | ((u32)(v0.y > 0.f) << (p * 8 + 1))
            | ((u32)(v1.x > 0.f) << (p * 8 + 2)) | ((u32)(v1.y > 0.f) << (p * 8 + 3))
            | ((u32)(v2.x > 0.f) << (p * 8 + 4)) | ((u32)(v2.y > 0.f) << (p * 8 + 5))
            | ((u32)(v3.x > 0.f) << (p * 8 + 6)) | ((u32)(v3.y > 0.f) << (p * 8 + 7));
        STORE_ACT(OFF_B, p, v0, v1, v2, v3, lk);
    }
    STS_TR(OFF_WA);
    __syncthreads();

    // -------- phase 4: L2 + head (B, WA) -> g in A; prefetch W2 -> WB row --------
    PREF_R(W2 + d * 4096);
#pragma unroll
    for (int p = 0; p < 4; ++p) {
        u64 bp = *(const u64*)(sm + OFF_SB2 + tys * 8 + 2 * p);
        acc[p * 4 + 0] = bp; acc[p * 4 + 1] = bp; acc[p * 4 + 2] = bp; acc[p * 4 + 3] = bp;
    }
    gemm8x4(sm + OFF_B, sm + OFF_WA, 64, txs, tys, acc);
    {
        float4 osum = make_float4(0.f, 0.f, 0.f, 0.f);
#pragma unroll
        for (int p = 0; p < 4; ++p) {
            float wl = sm[OFF_SWO + tys * 8 + 2 * p];
            float wh = sm[OFF_SWO + tys * 8 + 2 * p + 1];
            float2 v0 = unpk(acc[p * 4 + 0]), v1 = unpk(acc[p * 4 + 1]);
            float2 v2 = unpk(acc[p * 4 + 2]), v3 = unpk(acc[p * 4 + 3]);
            float gl0 = wl * (v0.x > 0.f ? 1.f : SLOPE), gh0 = wh * (v0.y > 0.f ? 1.f : SLOPE);
            float gl1 = wl * (v1.x > 0.f ? 1.f : SLOPE), gh1 = wh * (v1.y > 0.f ? 1.f : SLOPE);
            float gl2 = wl * (v2.x > 0.f ? 1.f : SLOPE), gh2 = wh * (v2.y > 0.f ? 1.f : SLOPE);
            float gl3 = wl * (v3.x > 0.f ? 1.f : SLOPE), gh3 = wh * (v3.y > 0.f ? 1.f : SLOPE);
            osum.x = fmaf(gl0, v0.x, fmaf(gh0, v0.y, osum.x));
            osum.y = fmaf(gl1, v1.x, fmaf(gh1, v1.y, osum.y));
            osum.z = fmaf(gl2, v2.x, fmaf(gh2, v2.y, osum.z));
            osum.w = fmaf(gl3, v3.x, fmaf(gh3, v3.y, osum.w));
            *(float4*)(sm + OFF_A + (tys * 8 + 2 * p) * SACT + txs * 4) =
                make_float4(gl0, gl1, gl2, gl3);
            *(float4*)(sm + OFF_A + (tys * 8 + 2 * p + 1) * SACT + txs * 4) =
                make_float4(gh0, gh1, gh2, gh3);
        }
        *(float4*)(sm + OFF_OUT + tys * 128 + txs * 4) = osum;
    }
    STS_R(OFF_WB);
    __syncthreads();

    // -------- phase 5: residuals; bwd2 (A, WB)*m1 -> B; prefetch W1 -> WA row --------
    if (tid < 128) {
        float r = bo_d;
#pragma unroll
        for (int q = 0; q < 8; ++q) r += sm[OFF_OUT + q * 128 + tid];
        out[(size_t)(tile * 128 + tid) * 8 + d] = r;
    }
    PREF_R(W1 + d * 4096);
#pragma unroll
    for (int i = 0; i < 16; ++i) acc[i] = 0ull;
    gemm8x4(sm + OFF_A, sm + OFF_WB, 64, txs, tys, acc);
#pragma unroll
    for (int p = 0; p < 4; ++p) {
        float2 v0 = unpk(acc[p * 4 + 0]), v1 = unpk(acc[p * 4 + 1]);
        float2 v2 = unpk(acc[p * 4 + 2]), v3 = unpk(acc[p * 4 + 3]);
        *(float4*)(sm + OFF_B + (tys * 8 + 2 * p) * SACT + txs * 4) =
            make_float4(v0.x * mb(m1, p * 8 + 0), v1.x * mb(m1, p * 8 + 2),
                        v2.x * mb(m1, p * 8 + 4), v3.x * mb(m1, p * 8 + 6));
        *(float4*)(sm + OFF_B + (tys * 8 + 2 * p + 1) * SACT + txs * 4) =
            make_float4(v0.y * mb(m1, p * 8 + 1), v1.y * mb(m1, p * 8 + 3),
                        v2.y * mb(m1, p * 8 + 5), v3.y * mb(m1, p * 8 + 7));
    }
    STS_R(OFF_WA);
    __syncthreads();

    // -------- phase 6: bwd1 (B, WA)*m0 -> A; prefetch W0 row (17 cols) -> WB --------
    float w0pre[5];
#pragma unroll
    for (int q = 0; q < 5; ++q) {
        int i = q * 256 + tid;
        w0pre[q] = (i < 1088) ? W0[d * 1088 + i] : 0.f;
    }
#pragma unroll
    for (int i = 0; i < 16; ++i) acc[i] = 0ull;
    gemm8x4(sm + OFF_B, sm + OFF_WA, 64, txs, tys, acc);
#pragma unroll
    for (int p = 0; p < 4; ++p) {
        float2 v0 = unpk(acc[p * 4 + 0]), v1 = unpk(acc[p * 4 + 1]);
        float2 v2 = unpk(acc[p * 4 + 2]), v3 = unpk(acc[p * 4 + 3]);
        *(float4*)(sm + OFF_A + (tys * 8 + 2 * p) * SACT + txs * 4) =
            make_float4(v0.x * mb(m0, p * 8 + 0), v1.x * mb(m0, p * 8 + 2),
                        v2.x * mb(m0, p * 8 + 4), v3.x * mb(m0, p * 8 + 6));
        *(float4*)(sm + OFF_A + (tys * 8 + 2 * p + 1) * SACT + txs * 4) =
            make_float4(v0.y * mb(m0, p * 8 + 1), v1.y * mb(m0, p * 8 + 3),
                        v2.y * mb(m0, p * 8 + 5), v3.y * mb(m0, p * 8 + 7));
    }
#pragma unroll
    for (int q = 0; q < 5; ++q) {
        int i = q * 256 + tid;
        if (i < 1088) {
            int h = i / 17, c = i - 17 * h;
            sm[OFF_WB + h * SW + c] = w0pre[q];
        }
    }
    __syncthreads();

    // -------- phase 7: jac = g1 @ W0 --------
    {
        const int tyj = tid >> 6;      // 0..3
        const int txj = tid & 63;      // 2 samples
        if (tyj < 2) {
            u64 a2[8];
#pragma unroll
            for (int i = 0; i < 8; ++i) a2[i] = 0ull;
            const float* ap = sm + OFF_A + txj * 2;
            const float* wp = sm + OFF_WB + tyj * 8;
#pragma unroll 4
            for (int k = 0; k < 64; ++k) {
                float2 a = *(const float2*)(ap + k * SACT);
                ulonglong2 wA = *(const ulonglong2*)(wp + k * SW);
                ulonglong2 wB = *(const ulonglong2*)(wp + k * SW + 4);
                u64 a0 = pack2(a.x, a.x), a1 = pack2(a.y, a.y);
                a2[0] = ffma2(wA.x, a0, a2[0]);  a2[1] = ffma2(wA.x, a1, a2[1]);
                a2[2] = ffma2(wA.y, a0, a2[2]);  a2[3] = ffma2(wA.y, a1, a2[3]);
                a2[4] = ffma2(wB.x, a0, a2[4]);  a2[5] = ffma2(wB.x, a1, a2[5]);
                a2[6] = ffma2(wB.y, a0, a2[6]);  a2[7] = ffma2(wB.y, a1, a2[7]);
            }
#pragma unroll
            for (int j = 0; j < 2; ++j) {
                int n = tile * 128 + txj * 2 + j;
                float2 p0 = unpk(a2[0 + j]), p1 = unpk(a2[2 + j]);
                float2 p2 = unpk(a2[4 + j]), p3 = unpk(a2[6 + j]);
                float* dst = out + 524416 + ((size_t)d * 65536 + n) * 16 + tyj * 8;
                *(float4*)dst       = make_float4(p0.x, p0.y, p1.x, p1.y);
                *(float4*)(dst + 4) = make_float4(p2.x, p2.y, p3.x, p3.y);
            }
        } else if (tyj == 2) {
            const float* ap = sm + OFF_A + txj * 2;
            const float* wp = sm + OFF_WB + 16;
            float s0 = 0.f, s1 = 0.f;
#pragma unroll 4
            for (int k = 0; k < 64; ++k) {
                float wv = wp[k * SW];
                float2 a = *(const float2*)(ap + k * SACT);
                s0 = fmaf(wv, a.x, s0);
                s1 = fmaf(wv, a.y, s1);
            }
            sm[OFF_J + txj] = logf(fabsf(s0)) + logf(fabsf(s1));
        }
    }
    __syncthreads();

    // -------- phase 8: publish partial; last block does the logdet reduce --------
    if (tid == 0) {
        float sj = 0.f;
#pragma unroll
        for (int q = 0; q < 64; ++q) sj += sm[OFF_J + q];
        g_partials[d * 512 + tile] = sj;
        __threadfence();
        u32 v = atomicAdd(&g_done, 1u);
        sm[OFF_FLAG] = (v == 4095u) ? 1.f : 0.f;
    }
    __syncthreads();
    if (sm[OFF_FLAG] != 0.f) {
        __threadfence();   // acquire: all g_partials writes are visible
        if (tid < 128) {
            const int b = tid;
            float s = 0.f;
#pragma unroll
            for (int dd = 0; dd < 8; ++dd)
#pragma unroll
                for (int q = 0; q < 4; ++q)
                    s += g_partials[dd * 512 + b * 4 + q];
            out[524288 + b] = s;
        }
        if (tid == 0) g_done = 0;   // reset for next graph replay
    }
}

extern "C" void kernel_launch(void* const* d_in, const int* in_sizes, int n_in,
                              void* d_out, int out_size) {
    const float* x  = (const float*)d_in[0];
    const float* W0 = (const float*)d_in[1];
    const float* b0 = (const float*)d_in[2];
    const float* W1 = (const float*)d_in[3];
    const float* b1 = (const float*)d_in[4];
    const float* W2 = (const float*)d_in[5];
    const float* b2 = (const float*)d_in[6];
    const float* Wo = (const float*)d_in[7];
    const float* bo = (const float*)d_in[8];
    float* out = (float*)d_out;

    cudaFuncSetAttribute(mlp_tile_kernel,
                         cudaFuncAttributeMaxDynamicSharedMemorySize, SMEM_BYTES);
    dim3 grid(512, 8);
    mlp_tile_kernel<<<grid, 256, SMEM_BYTES>>>(x, W0, b0, W1, b1, W2, b2, Wo, bo, out);
}